// round 7
// baseline (speedup 1.0000x reference)
#include <cuda_runtime.h>
#include <math.h>
#include <stdint.h>

#define BB 4
#define TT 8192
#define NV 64
#define FF 16
#define CC 1024   // NV*FF
#define OO 32
#define NCAT 96   // 3 taps * 32 outputs

// ---------------- scratch (static device globals; no allocation) -------------
__device__ __align__(16) float g_lhs[BB*NV*FF];
__device__ __align__(16) float g_R2 [BB*NV*FF];
__device__ __align__(16) float g_S  [BB*NV*NV];
__device__ __align__(16) float g_WT [BB*NCAT*CC];         // WT[b][oc][c], tf32-rounded
__device__ __align__(16) float g_G  [(size_t)BB*TT*NCAT]; // G[b][t][oc]

// ---------------- helpers -----------------------------------------------------
__device__ __forceinline__ uint32_t smem_u32(const void* p) {
    uint32_t a;
    asm("{ .reg .u64 t; cvta.to.shared.u64 t, %1; cvt.u32.u64 %0, t; }"
        : "=r"(a) : "l"(p));
    return a;
}
__device__ __forceinline__ void cp16(uint32_t dst, const void* src) {
    asm volatile("cp.async.cg.shared.global [%0], [%1], 16;"
                 :: "r"(dst), "l"(src) : "memory");
}
__device__ __forceinline__ void cp_commit() {
    asm volatile("cp.async.commit_group;" ::: "memory");
}
template<int N> __device__ __forceinline__ void cp_wait() {
    asm volatile("cp.async.wait_group %0;" :: "n"(N) : "memory");
}
__device__ __forceinline__ uint32_t f2tf32(float f) {
    uint32_t u;
    asm("cvt.rna.tf32.f32 %0, %1;" : "=r"(u) : "f"(f));
    return u;
}
__device__ __forceinline__ void mma_tf32(float* d, const uint32_t* a,
                                         const uint32_t* bfr) {
    asm volatile(
        "mma.sync.aligned.m16n8k8.row.col.f32.tf32.tf32.f32 "
        "{%0,%1,%2,%3}, {%4,%5,%6,%7}, {%8,%9}, {%0,%1,%2,%3};"
        : "+f"(d[0]), "+f"(d[1]), "+f"(d[2]), "+f"(d[3])
        : "r"(a[0]), "r"(a[1]), "r"(a[2]), "r"(a[3]),
          "r"(bfr[0]), "r"(bfr[1]));
}

// ---------------- kernel 0: zero accumulators --------------------------------
__global__ void k_zero() {
    int i = blockIdx.x*blockDim.x + threadIdx.x;
    if (i < BB*NV*FF) { g_lhs[i] = 0.f; g_R2[i] = 0.f; }
}

// ---------------- kernel 1: streaming reductions over T -----------------------
__global__ void __launch_bounds__(256) k1_reduce(
    const float* __restrict__ x, const float* __restrict__ W1,
    const float* __restrict__ W2, const float* __restrict__ W3)
{
    const int b  = blockIdx.y;
    const int t0 = blockIdx.x * 128;
    const int j  = threadIdx.x;
    const int n  = j >> 2;
    const int f0 = (j & 3) * 4;

    __shared__ __align__(16) float sW1[128];
    __shared__ __align__(16) float sW2[16][129];

    if (j < 128) sW1[j] = W1[t0 + j];
    for (int idx = j; idx < 16*128; idx += 256) {
        int f = idx >> 7, tt = idx & 127;
        sW2[f][tt] = W2[f*TT + t0 + tt];
    }
    float w3v[4];
    #pragma unroll
    for (int d = 0; d < 4; d++) w3v[d] = W3[f0 + d];
    __syncthreads();

    float lhsacc[4] = {0,0,0,0};
    float r2acc[4]  = {0,0,0,0};
    const float4* xr = reinterpret_cast<const float4*>(
        x + (size_t)b*TT*CC + (size_t)t0*CC) + j;

    for (int tt = 0; tt < 128; tt++) {
        float4 xv = xr[(size_t)tt*256];
        float s3 = xv.x*w3v[0] + xv.y*w3v[1] + xv.z*w3v[2] + xv.w*w3v[3];
        s3 += __shfl_xor_sync(0xffffffffu, s3, 1);
        s3 += __shfl_xor_sync(0xffffffffu, s3, 2);
        float w1 = sW1[tt];
        lhsacc[0] += w1*xv.x; lhsacc[1] += w1*xv.y;
        lhsacc[2] += w1*xv.z; lhsacc[3] += w1*xv.w;
        #pragma unroll
        for (int d = 0; d < 4; d++) r2acc[d] += sW2[f0+d][tt] * s3;
    }
    #pragma unroll
    for (int d = 0; d < 4; d++) {
        atomicAdd(&g_lhs[(b*NV + n)*FF + f0 + d], lhsacc[d]);
        atomicAdd(&g_R2 [(b*NV + n)*FF + f0 + d], r2acc[d]);
    }
}

// ---------------- kernel 2a: attention matrix S -------------------------------
__global__ void __launch_bounds__(256) k2a_S(
    const float* __restrict__ bs, const float* __restrict__ Vs)
{
    const int b = blockIdx.x;
    const int tid = threadIdx.x;
    __shared__ __align__(16) float lhs_s[NV*FF];
    __shared__ __align__(16) float R2_s [NV*FF];
    __shared__ __align__(16) float P_s  [NV*NV];
    __shared__ __align__(16) float S0_s [NV*NV];

    for (int i = tid; i < NV*FF; i += 256) {
        lhs_s[i] = g_lhs[b*NV*FF + i];
        R2_s[i]  = g_R2 [b*NV*FF + i];
    }
    __syncthreads();

    for (int i = tid; i < NV*NV; i += 256) {
        int m = i >> 6, k = i & 63;
        float acc = 0.f;
        #pragma unroll
        for (int f = 0; f < FF; f++) acc += lhs_s[m*FF+f] * R2_s[k*FF+f];
        acc += bs[i];
        P_s[i] = 1.f / (1.f + expf(-acc));
    }
    __syncthreads();

    for (int i = tid; i < NV*NV; i += 256) {
        int nn = i >> 6, k = i & 63;
        float acc = 0.f;
        #pragma unroll 8
        for (int m = 0; m < NV; m++) acc += Vs[nn*NV+m] * P_s[m*NV+k];
        S0_s[i] = acc;
    }
    __syncthreads();

    if (tid < NV) {
        const int k = tid;
        float mx = -1e30f;
        for (int nn = 0; nn < NV; nn++) mx = fmaxf(mx, S0_s[nn*NV+k]);
        float sum = 0.f;
        for (int nn = 0; nn < NV; nn++) sum += expf(S0_s[nn*NV+k] - mx);
        float inv = 1.f / sum;
        for (int nn = 0; nn < NV; nn++)
            g_S[b*NV*NV + nn*NV + k] = expf(S0_s[nn*NV+k] - mx) * inv;
    }
}

// ---------------- kernel 2b: WT via f-sliced mini-GEMM -------------------------
// grid (16, BB), 256 threads. Out_f[m][oc] = sum_n Sd[m][n] * CWf[n][oc],
// CWf[n][tap*32+o] = conv_w[o][(n*16+f)][tap].
// Thread = (m = tid>>2, oq = tid&3) computes 24 oc with full ILP.
__global__ void __launch_bounds__(256) k2b_wt(
    const float* __restrict__ adj, const float* __restrict__ conv_w)
{
    const int f = blockIdx.x, b = blockIdx.y;
    const int tid = threadIdx.x;
    __shared__ __align__(16) float Sd[NV*NV];      // [m][n]
    __shared__ __align__(16) float CWf[NV][NCAT];  // [n][oc], 384B rows

    for (int i = tid; i < NV*NV; i += 256) {
        int nn = i & 63;
        Sd[i] = g_S[b*NV*NV + i] * adj[nn*NV + nn];
    }
    for (int i = tid; i < NV*NCAT; i += 256) {
        int n = i / NCAT, oc = i - n*NCAT;
        int tap = oc >> 5, o = oc & 31;
        CWf[n][oc] = conv_w[(size_t)o*CC*3 + (n*FF + f)*3 + tap];
    }
    __syncthreads();

    const int m = tid >> 2, oq = tid & 3, oc0 = oq * 24;
    float acc[24];
    #pragma unroll
    for (int j = 0; j < 24; j++) acc[j] = 0.f;

    for (int n = 0; n < NV; n++) {
        float s = Sd[m*NV + n];
        const float4* cw4 = reinterpret_cast<const float4*>(&CWf[n][oc0]);
        #pragma unroll
        for (int q = 0; q < 6; q++) {
            float4 w = cw4[q];
            acc[q*4+0] += s*w.x; acc[q*4+1] += s*w.y;
            acc[q*4+2] += s*w.z; acc[q*4+3] += s*w.w;
        }
    }

    #pragma unroll
    for (int j = 0; j < 24; j++) {
        int oc = oc0 + j;
        g_WT[((size_t)b*NCAT + oc)*CC + m*FF + f] =
            __uint_as_float(f2tf32(acc[j]));
    }
}

// ---------------- kernel 3: G = x @ WT^T via mma.sync tf32 --------------------
// grid (TT/128, BB), 128 threads (4 warps). Warp: 32 rows x 96 cols.
// Free k-permutation: mma step ks, position (t4,h) <- physical col 8*t4+2*ks+h,
// so each thread's fragments for ALL 4 k-steps = phys cols [8*t4, 8*t4+8) of
// its rows -> 2x LDS.128 per row, conflict-free with ROWP=36.
#define MT   128
#define KC   32
#define NSTG (CC/KC)          // 32
#define ROWP 36               // floats per smem row (9 float4)
#define XOFF0 0
#define WOFF0 (MT*ROWP*4)                 // 18432 B
#define XOFF1 (WOFF0 + NCAT*ROWP*4)       // 32256 B
#define WOFF1 (XOFF1 + MT*ROWP*4)         // 50688 B
#define SMEM_K3 (WOFF1 + NCAT*ROWP*4)     // 64512 B

__global__ void __launch_bounds__(128) k3_mma(const float* __restrict__ x)
{
    extern __shared__ __align__(16) float smemf[];
    const uint32_t sb = smem_u32(smemf);
    const int tid  = threadIdx.x;
    const int wid  = tid >> 5, lane = tid & 31;
    const int g    = lane >> 2;           // 0..7
    const int t4   = lane & 3;            // 0..3
    const int b    = blockIdx.y;
    const size_t m0 = (size_t)blockIdx.x * MT;

    const char* xg = (const char*)(x + ((size_t)b*TT + m0)*CC);
    const char* wg = (const char*)(g_WT + (size_t)b*NCAT*CC);

    float acc[2][12][4];
    #pragma unroll
    for (int mi = 0; mi < 2; mi++)
        #pragma unroll
        for (int j = 0; j < 12; j++)
            #pragma unroll
            for (int d = 0; d < 4; d++) acc[mi][j][d] = 0.f;

    #define LOAD_STAGE(s) do {                                                  \
        uint32_t xd = sb + (((s)&1) ? XOFF1 : XOFF0);                           \
        uint32_t wd = sb + (((s)&1) ? WOFF1 : WOFF0);                           \
        int c0b = (s)*KC*4;                                                     \
        _Pragma("unroll")                                                       \
        for (int i = 0; i < 8; i++) {                                           \
            int idx = tid + i*128; int row = idx >> 3, q = idx & 7;             \
            cp16(xd + row*(ROWP*4) + q*16, xg + (size_t)row*CC*4 + c0b + q*16); \
        }                                                                       \
        _Pragma("unroll")                                                       \
        for (int i = 0; i < 6; i++) {                                           \
            int idx = tid + i*128; int row = idx >> 3, q = idx & 7;             \
            cp16(wd + row*(ROWP*4) + q*16, wg + (size_t)row*CC*4 + c0b + q*16); \
        }                                                                       \
        cp_commit();                                                            \
    } while (0)

    LOAD_STAGE(0);

    const int wr = wid * 32;
    const int f4q = t4 * 2;   // float4 index of this thread's 8-col window

    for (int s = 0; s < NSTG; s++) {
        cp_wait<0>();          // only this stage's group is pending
        __syncthreads();       // data visible; all warps done with prev compute
        if (s + 1 < NSTG) LOAD_STAGE(s + 1);   // other buffer, now safe

        const float4* xs4 = reinterpret_cast<const float4*>(
            (const char*)smemf + ((s&1) ? XOFF1 : XOFF0));
        const float4* ws4 = reinterpret_cast<const float4*>(
            (const char*)smemf + ((s&1) ? WOFF1 : WOFF0));

        // A fragments: [mi][row01][8 phys cols], tf32-rounded
        uint32_t ae[2][2][8];
        #pragma unroll
        for (int mi = 0; mi < 2; mi++) {
            #pragma unroll
            for (int r = 0; r < 2; r++) {
                int row = wr + mi*16 + r*8 + g;
                float4 lo = xs4[row*9 + f4q];
                float4 hi = xs4[row*9 + f4q + 1];
                ae[mi][r][0] = f2tf32(lo.x); ae[mi][r][1] = f2tf32(lo.y);
                ae[mi][r][2] = f2tf32(lo.z); ae[mi][r][3] = f2tf32(lo.w);
                ae[mi][r][4] = f2tf32(hi.x); ae[mi][r][5] = f2tf32(hi.y);
                ae[mi][r][6] = f2tf32(hi.z); ae[mi][r][7] = f2tf32(hi.w);
            }
        }

        #pragma unroll
        for (int j = 0; j < 12; j++) {
            int nr = 8*j + g;
            float4 blo = ws4[nr*9 + f4q];
            float4 bhi = ws4[nr*9 + f4q + 1];
            uint32_t be[8] = {
                __float_as_uint(blo.x), __float_as_uint(blo.y),
                __float_as_uint(blo.z), __float_as_uint(blo.w),
                __float_as_uint(bhi.x), __float_as_uint(bhi.y),
                __float_as_uint(bhi.z), __float_as_uint(bhi.w) };
            #pragma unroll
            for (int ks = 0; ks < 4; ks++) {
                uint32_t b2[2] = { be[2*ks], be[2*ks+1] };
                #pragma unroll
                for (int mi = 0; mi < 2; mi++) {
                    uint32_t a4[4] = { ae[mi][0][2*ks],   ae[mi][1][2*ks],
                                       ae[mi][0][2*ks+1], ae[mi][1][2*ks+1] };
                    mma_tf32(acc[mi][j], a4, b2);
                }
            }
        }
    }

    // epilogue: C frag (rows g/g+8, cols 2*t4, 2*t4+1) per 16x8 tile
    float* gr = g_G + ((size_t)b*TT + m0 + (size_t)wid*32)*NCAT;
    #pragma unroll
    for (int mi = 0; mi < 2; mi++) {
        #pragma unroll
        for (int j = 0; j < 12; j++) {
            int col = 8*j + 2*t4;
            int r0 = mi*16 + g;
            *reinterpret_cast<float2*>(gr + (size_t)r0*NCAT + col) =
                make_float2(acc[mi][j][0], acc[mi][j][1]);
            *reinterpret_cast<float2*>(gr + (size_t)(r0+8)*NCAT + col) =
                make_float2(acc[mi][j][2], acc[mi][j][3]);
        }
    }
}

// ---------------- kernel 4: out[t,o] = G[t-1,o] + G[t,32+o] + G[t+1,64+o] -----
__global__ void __launch_bounds__(256) k4_combine(float* __restrict__ out)
{
    const int b = blockIdx.y;
    const int idx = blockIdx.x*256 + threadIdx.x;   // over TT*8
    const int t = idx >> 3, q = idx & 7;
    const float* Gb = g_G + (size_t)b*TT*NCAT;

    float4 acc = make_float4(0.f, 0.f, 0.f, 0.f);
    if (t > 0) {
        float4 v = *reinterpret_cast<const float4*>(Gb + (size_t)(t-1)*NCAT + q*4);
        acc.x += v.x; acc.y += v.y; acc.z += v.z; acc.w += v.w;
    }
    {
        float4 v = *reinterpret_cast<const float4*>(Gb + (size_t)t*NCAT + 32 + q*4);
        acc.x += v.x; acc.y += v.y; acc.z += v.z; acc.w += v.w;
    }
    if (t < TT-1) {
        float4 v = *reinterpret_cast<const float4*>(Gb + (size_t)(t+1)*NCAT + 64 + q*4);
        acc.x += v.x; acc.y += v.y; acc.z += v.z; acc.w += v.w;
    }
    *reinterpret_cast<float4*>(out + ((size_t)b*TT + t)*OO + q*4) = acc;
}

// ---------------- launch ------------------------------------------------------
extern "C" void kernel_launch(void* const* d_in, const int* in_sizes, int n_in,
                              void* d_out, int out_size)
{
    const float* x      = (const float*)d_in[0];
    const float* adj    = (const float*)d_in[1];
    const float* W1     = (const float*)d_in[2];
    const float* W2     = (const float*)d_in[3];
    const float* W3     = (const float*)d_in[4];
    const float* bs     = (const float*)d_in[5];
    const float* Vs     = (const float*)d_in[6];
    const float* conv_w = (const float*)d_in[7];
    float* out = (float*)d_out;

    cudaFuncSetAttribute(k3_mma, cudaFuncAttributeMaxDynamicSharedMemorySize,
                         SMEM_K3);

    k_zero<<<16, 256>>>();
    k1_reduce<<<dim3(TT/128, BB), 256>>>(x, W1, W2, W3);
    k2a_S<<<BB, 256>>>(bs, Vs);
    k2b_wt<<<dim3(FF, BB), 256>>>(adj, conv_w);
    k3_mma<<<dim3(TT/MT, BB), 128, SMEM_K3>>>(x);
    k4_combine<<<dim3(TT*8/256, BB), 256>>>(out);
}

// round 11
// speedup vs baseline: 1.0022x; 1.0022x over previous
#include <cuda_runtime.h>
#include <math.h>
#include <stdint.h>

#define BB 4
#define TT 8192
#define NV 64
#define FF 16
#define CC 1024   // NV*FF
#define OO 32
#define NCAT 96   // 3 taps * 32 outputs
#define NBLK 64   // k1 blocks per batch

// ---------------- scratch (static device globals; no allocation) -------------
__device__ __align__(16) float g_pl [BB*NBLK*CC];         // k1 partial lhs
__device__ __align__(16) float g_pr [BB*NBLK*CC];         // k1 partial r2
__device__ __align__(16) float g_S  [BB*NV*NV];
__device__ __align__(16) float g_WT [BB*NCAT*CC];         // WT[b][oc][c], tf32-rounded
__device__ __align__(16) float g_G  [(size_t)BB*TT*NCAT]; // G[b][t][oc]

// ---------------- helpers -----------------------------------------------------
__device__ __forceinline__ uint32_t smem_u32(const void* p) {
    uint32_t a;
    asm("{ .reg .u64 t; cvta.to.shared.u64 t, %1; cvt.u32.u64 %0, t; }"
        : "=r"(a) : "l"(p));
    return a;
}
__device__ __forceinline__ void cp16(uint32_t dst, const void* src) {
    asm volatile("cp.async.cg.shared.global [%0], [%1], 16;"
                 :: "r"(dst), "l"(src) : "memory");
}
__device__ __forceinline__ void cp_commit() {
    asm volatile("cp.async.commit_group;" ::: "memory");
}
template<int N> __device__ __forceinline__ void cp_wait() {
    asm volatile("cp.async.wait_group %0;" :: "n"(N) : "memory");
}
__device__ __forceinline__ uint32_t f2tf32(float f) {
    uint32_t u;
    asm("cvt.rna.tf32.f32 %0, %1;" : "=r"(u) : "f"(f));
    return u;
}
__device__ __forceinline__ void mma_tf32(float* d, const uint32_t* a,
                                         const uint32_t* bfr) {
    asm volatile(
        "mma.sync.aligned.m16n8k8.row.col.f32.tf32.tf32.f32 "
        "{%0,%1,%2,%3}, {%4,%5,%6,%7}, {%8,%9}, {%0,%1,%2,%3};"
        : "+f"(d[0]), "+f"(d[1]), "+f"(d[2]), "+f"(d[3])
        : "r"(a[0]), "r"(a[1]), "r"(a[2]), "r"(a[3]),
          "r"(bfr[0]), "r"(bfr[1]));
}

// ---------------- kernel 1: streaming reductions -> per-block partials --------
__global__ void __launch_bounds__(256) k1_reduce(
    const float* __restrict__ x, const float* __restrict__ W1,
    const float* __restrict__ W2, const float* __restrict__ W3)
{
    const int b  = blockIdx.y;
    const int t0 = blockIdx.x * 128;
    const int j  = threadIdx.x;
    const int f0 = (j & 3) * 4;

    __shared__ __align__(16) float sW1[128];
    __shared__ __align__(16) float sW2[16][129];

    if (j < 128) sW1[j] = W1[t0 + j];
    for (int idx = j; idx < 16*128; idx += 256) {
        int f = idx >> 7, tt = idx & 127;
        sW2[f][tt] = W2[f*TT + t0 + tt];
    }
    float w3v[4];
    #pragma unroll
    for (int d = 0; d < 4; d++) w3v[d] = W3[f0 + d];
    __syncthreads();

    float lhsacc[4] = {0,0,0,0};
    float r2acc[4]  = {0,0,0,0};
    const float4* xr = reinterpret_cast<const float4*>(
        x + (size_t)b*TT*CC + (size_t)t0*CC) + j;

    #pragma unroll 4
    for (int tt = 0; tt < 128; tt++) {
        float4 xv = xr[(size_t)tt*256];
        float s3 = xv.x*w3v[0] + xv.y*w3v[1] + xv.z*w3v[2] + xv.w*w3v[3];
        s3 += __shfl_xor_sync(0xffffffffu, s3, 1);
        s3 += __shfl_xor_sync(0xffffffffu, s3, 2);
        float w1 = sW1[tt];
        lhsacc[0] += w1*xv.x; lhsacc[1] += w1*xv.y;
        lhsacc[2] += w1*xv.z; lhsacc[3] += w1*xv.w;
        #pragma unroll
        for (int d = 0; d < 4; d++) r2acc[d] += sW2[f0+d][tt] * s3;
    }

    // channel c = 4*j + d
    size_t base = ((size_t)b*NBLK + blockIdx.x)*CC + j*4;
    *reinterpret_cast<float4*>(g_pl + base) =
        make_float4(lhsacc[0], lhsacc[1], lhsacc[2], lhsacc[3]);
    *reinterpret_cast<float4*>(g_pr + base) =
        make_float4(r2acc[0], r2acc[1], r2acc[2], r2acc[3]);
}

// ---------------- kernel 2a: reduce partials + attention matrix S -------------
__global__ void __launch_bounds__(256) k2a_S(
    const float* __restrict__ bs, const float* __restrict__ Vs)
{
    const int b = blockIdx.x;
    const int tid = threadIdx.x;
    __shared__ __align__(16) float lhs_s[NV*FF];
    __shared__ __align__(16) float R2_s [NV*FF];
    __shared__ __align__(16) float P_s  [NV*NV];
    __shared__ __align__(16) float S0_s [NV*NV];

    // reduce 64 partials: thread tid owns float4 column tid (CC/4 = 256)
    {
        const float4* pl = reinterpret_cast<const float4*>(g_pl) + (size_t)b*NBLK*256;
        const float4* pr = reinterpret_cast<const float4*>(g_pr) + (size_t)b*NBLK*256;
        float4 al = make_float4(0,0,0,0), ar = make_float4(0,0,0,0);
        #pragma unroll 8
        for (int blk = 0; blk < NBLK; blk++) {
            float4 v = pl[blk*256 + tid];
            al.x += v.x; al.y += v.y; al.z += v.z; al.w += v.w;
            float4 w = pr[blk*256 + tid];
            ar.x += w.x; ar.y += w.y; ar.z += w.z; ar.w += w.w;
        }
        *reinterpret_cast<float4*>(lhs_s + tid*4) = al;
        *reinterpret_cast<float4*>(R2_s  + tid*4) = ar;
    }
    __syncthreads();

    for (int i = tid; i < NV*NV; i += 256) {
        int m = i >> 6, k = i & 63;
        float acc = 0.f;
        #pragma unroll
        for (int f = 0; f < FF; f++) acc += lhs_s[m*FF+f] * R2_s[k*FF+f];
        acc += bs[i];
        P_s[i] = 1.f / (1.f + expf(-acc));
    }
    __syncthreads();

    for (int i = tid; i < NV*NV; i += 256) {
        int nn = i >> 6, k = i & 63;
        float acc = 0.f;
        #pragma unroll 8
        for (int m = 0; m < NV; m++) acc += Vs[nn*NV+m] * P_s[m*NV+k];
        S0_s[i] = acc;
    }
    __syncthreads();

    if (tid < NV) {
        const int k = tid;
        float mx = -1e30f;
        for (int nn = 0; nn < NV; nn++) mx = fmaxf(mx, S0_s[nn*NV+k]);
        float sum = 0.f;
        for (int nn = 0; nn < NV; nn++) sum += expf(S0_s[nn*NV+k] - mx);
        float inv = 1.f / sum;
        for (int nn = 0; nn < NV; nn++)
            g_S[b*NV*NV + nn*NV + k] = expf(S0_s[nn*NV+k] - mx) * inv;
    }
}

// ---------------- kernel 2b: WT, grid (O, B), coalesced conv_w ----------------
// WT[b][tap*32+o][m*16+f] = sum_n SdT[n][m] * cws[(n*16+f)*3+tap]
__global__ void __launch_bounds__(256) k2b_wt(
    const float* __restrict__ adj, const float* __restrict__ conv_w)
{
    const int o = blockIdx.x, b = blockIdx.y;
    const int tid = threadIdx.x;
    __shared__ __align__(16) float cws[CC*3];      // conv_w[o][c][tap], 12 KB
    __shared__ __align__(16) float SdT[NV*65];     // [n][m], pad-65

    for (int i = tid; i < CC*3; i += 256)
        cws[i] = conv_w[(size_t)o*CC*3 + i];
    for (int i = tid; i < NV*NV; i += 256) {
        int m = i >> 6, nn = i & 63;               // read g_S coalesced
        SdT[nn*65 + m] = g_S[b*NV*NV + i] * adj[nn*NV + nn];
    }
    __syncthreads();

    const int c0 = tid * 4;                        // 4 consecutive c, same m
    const int m = c0 >> 4, f0 = c0 & 15;
    float acc[3][4];
    #pragma unroll
    for (int t = 0; t < 3; t++)
        #pragma unroll
        for (int j = 0; j < 4; j++) acc[t][j] = 0.f;

    #pragma unroll 4
    for (int n = 0; n < NV; n++) {
        float s = SdT[n*65 + m];
        const float4* cw4 = reinterpret_cast<const float4*>(
            cws + (n*FF + f0)*3);                  // 12 floats, 16B-aligned
        float4 w0 = cw4[0], w1 = cw4[1], w2 = cw4[2];
        acc[0][0] += s*w0.x; acc[1][0] += s*w0.y; acc[2][0] += s*w0.z;
        acc[0][1] += s*w0.w; acc[1][1] += s*w1.x; acc[2][1] += s*w1.y;
        acc[0][2] += s*w1.z; acc[1][2] += s*w1.w; acc[2][2] += s*w2.x;
        acc[0][3] += s*w2.y; acc[1][3] += s*w2.z; acc[2][3] += s*w2.w;
    }

    #pragma unroll
    for (int t = 0; t < 3; t++) {
        float4 v = make_float4(
            __uint_as_float(f2tf32(acc[t][0])), __uint_as_float(f2tf32(acc[t][1])),
            __uint_as_float(f2tf32(acc[t][2])), __uint_as_float(f2tf32(acc[t][3])));
        *reinterpret_cast<float4*>(
            g_WT + ((size_t)b*NCAT + t*OO + o)*CC + c0) = v;
    }
}

// ---------------- kernel 3: G = x @ WT^T via mma.sync tf32, 3-stage pipe ------
#define MT   128
#define KC   32
#define NSTG (CC/KC)          // 32
#define ROWP 36               // floats per smem row (9 float4)
#define XSZ  (MT*ROWP*4)      // 18432 B
#define WSZ  (NCAT*ROWP*4)    // 13824 B
#define BUFSZ (XSZ + WSZ)     // 32256 B
#define SMEM_K3 (3*BUFSZ)     // 96768 B

__global__ void __launch_bounds__(128) k3_mma(const float* __restrict__ x)
{
    extern __shared__ __align__(16) float smemf[];
    const uint32_t sb = smem_u32(smemf);
    const int tid  = threadIdx.x;
    const int wid  = tid >> 5, lane = tid & 31;
    const int g    = lane >> 2;           // 0..7
    const int t4   = lane & 3;            // 0..3
    const int b    = blockIdx.y;
    const size_t m0 = (size_t)blockIdx.x * MT;

    const char* xg = (const char*)(x + ((size_t)b*TT + m0)*CC);
    const char* wg = (const char*)(g_WT + (size_t)b*NCAT*CC);

    float acc[2][12][4];
    #pragma unroll
    for (int mi = 0; mi < 2; mi++)
        #pragma unroll
        for (int j = 0; j < 12; j++)
            #pragma unroll
            for (int d = 0; d < 4; d++) acc[mi][j][d] = 0.f;

    #define LOAD_STAGE(s) do {                                                  \
        uint32_t bd_ = sb + ((s) % 3) * BUFSZ;                                  \
        int c0b = (s)*KC*4;                                                     \
        _Pragma("unroll")                                                       \
        for (int i = 0; i < 8; i++) {                                           \
            int idx = tid + i*128; int row = idx >> 3, q = idx & 7;             \
            cp16(bd_ + row*(ROWP*4) + q*16, xg + (size_t)row*CC*4 + c0b + q*16);\
        }                                                                       \
        _Pragma("unroll")                                                       \
        for (int i = 0; i < 6; i++) {                                           \
            int idx = tid + i*128; int row = idx >> 3, q = idx & 7;             \
            cp16(bd_ + XSZ + row*(ROWP*4) + q*16,                               \
                 wg + (size_t)row*CC*4 + c0b + q*16);                           \
        }                                                                       \
        cp_commit();                                                            \
    } while (0)

    LOAD_STAGE(0);
    LOAD_STAGE(1);

    const int wr = wid * 32;
    const int f4q = t4 * 2;

    for (int s = 0; s < NSTG; s++) {
        if (s + 1 < NSTG) cp_wait<1>();   // stage s complete, s+1 may fly
        else              cp_wait<0>();
        __syncthreads();                  // all warps past stage s-1 compute
        if (s + 2 < NSTG) LOAD_STAGE(s + 2);   // buffer (s+2)%3 is free

        const float4* xs4 = reinterpret_cast<const float4*>(
            (const char*)smemf + (s % 3) * BUFSZ);
        const float4* ws4 = reinterpret_cast<const float4*>(
            (const char*)smemf + (s % 3) * BUFSZ + XSZ);

        uint32_t ae[2][2][8];
        #pragma unroll
        for (int mi = 0; mi < 2; mi++) {
            #pragma unroll
            for (int r = 0; r < 2; r++) {
                int row = wr + mi*16 + r*8 + g;
                float4 lo = xs4[row*9 + f4q];
                float4 hi = xs4[row*9 + f4q + 1];
                ae[mi][r][0] = f2tf32(lo.x); ae[mi][r][1] = f2tf32(lo.y);
                ae[mi][r][2] = f2tf32(lo.z); ae[mi][r][3] = f2tf32(lo.w);
                ae[mi][r][4] = f2tf32(hi.x); ae[mi][r][5] = f2tf32(hi.y);
                ae[mi][r][6] = f2tf32(hi.z); ae[mi][r][7] = f2tf32(hi.w);
            }
        }

        #pragma unroll
        for (int j = 0; j < 12; j++) {
            int nr = 8*j + g;
            float4 blo = ws4[nr*9 + f4q];
            float4 bhi = ws4[nr*9 + f4q + 1];
            uint32_t be[8] = {
                __float_as_uint(blo.x), __float_as_uint(blo.y),
                __float_as_uint(blo.z), __float_as_uint(blo.w),
                __float_as_uint(bhi.x), __float_as_uint(bhi.y),
                __float_as_uint(bhi.z), __float_as_uint(bhi.w) };
            #pragma unroll
            for (int ks = 0; ks < 4; ks++) {
                uint32_t b2[2] = { be[2*ks], be[2*ks+1] };
                #pragma unroll
                for (int mi = 0; mi < 2; mi++) {
                    uint32_t a4[4] = { ae[mi][0][2*ks],   ae[mi][1][2*ks],
                                       ae[mi][0][2*ks+1], ae[mi][1][2*ks+1] };
                    mma_tf32(acc[mi][j], a4, b2);
                }
            }
        }
    }

    float* gr = g_G + ((size_t)b*TT + m0 + (size_t)wid*32)*NCAT;
    #pragma unroll
    for (int mi = 0; mi < 2; mi++) {
        #pragma unroll
        for (int j = 0; j < 12; j++) {
            int col = 8*j + 2*t4;
            int r0 = mi*16 + g;
            *reinterpret_cast<float2*>(gr + (size_t)r0*NCAT + col) =
                make_float2(acc[mi][j][0], acc[mi][j][1]);
            *reinterpret_cast<float2*>(gr + (size_t)(r0+8)*NCAT + col) =
                make_float2(acc[mi][j][2], acc[mi][j][3]);
        }
    }
}

// ---------------- kernel 4: out[t,o] = G[t-1,o] + G[t,32+o] + G[t+1,64+o] -----
__global__ void __launch_bounds__(256) k4_combine(float* __restrict__ out)
{
    const int b = blockIdx.y;
    const int idx = blockIdx.x*256 + threadIdx.x;   // over TT*8
    const int t = idx >> 3, q = idx & 7;
    const float* Gb = g_G + (size_t)b*TT*NCAT;

    float4 acc = make_float4(0.f, 0.f, 0.f, 0.f);
    if (t > 0) {
        float4 v = *reinterpret_cast<const float4*>(Gb + (size_t)(t-1)*NCAT + q*4);
        acc.x += v.x; acc.y += v.y; acc.z += v.z; acc.w += v.w;
    }
    {
        float4 v = *reinterpret_cast<const float4*>(Gb + (size_t)t*NCAT + 32 + q*4);
        acc.x += v.x; acc.y += v.y; acc.z += v.z; acc.w += v.w;
    }
    if (t < TT-1) {
        float4 v = *reinterpret_cast<const float4*>(Gb + (size_t)(t+1)*NCAT + 64 + q*4);
        acc.x += v.x; acc.y += v.y; acc.z += v.z; acc.w += v.w;
    }
    *reinterpret_cast<float4*>(out + ((size_t)b*TT + t)*OO + q*4) = acc;
}

// ---------------- launch ------------------------------------------------------
extern "C" void kernel_launch(void* const* d_in, const int* in_sizes, int n_in,
                              void* d_out, int out_size)
{
    const float* x      = (const float*)d_in[0];
    const float* adj    = (const float*)d_in[1];
    const float* W1     = (const float*)d_in[2];
    const float* W2     = (const float*)d_in[3];
    const float* W3     = (const float*)d_in[4];
    const float* bs     = (const float*)d_in[5];
    const float* Vs     = (const float*)d_in[6];
    const float* conv_w = (const float*)d_in[7];
    float* out = (float*)d_out;

    cudaFuncSetAttribute(k3_mma, cudaFuncAttributeMaxDynamicSharedMemorySize,
                         SMEM_K3);

    k1_reduce<<<dim3(NBLK, BB), 256>>>(x, W1, W2, W3);   // idx 0
    k2a_S<<<BB, 256>>>(bs, Vs);                          // idx 1
    k2b_wt<<<dim3(OO, BB), 256>>>(adj, conv_w);          // idx 2
    k3_mma<<<dim3(TT/MT, BB), 128, SMEM_K3>>>(x);        // idx 3  <- ncu window
    k4_combine<<<dim3(TT*8/256, BB), 256>>>(out);        // idx 4
}

// round 12
// speedup vs baseline: 1.0599x; 1.0576x over previous
#include <cuda_runtime.h>
#include <math.h>
#include <stdint.h>

#define BB 4
#define TT 8192
#define NV 64
#define FF 16
#define CC 1024   // NV*FF
#define OO 32
#define NCAT 96   // 3 taps * 32 outputs
#define NBLK 64   // k1 blocks per batch

// ---------------- scratch (static device globals; no allocation) -------------
__device__ __align__(16) float g_pl [BB*NBLK*CC];         // k1 partial lhs
__device__ __align__(16) float g_pr [BB*NBLK*CC];         // k1 partial r2
__device__ __align__(16) float g_S  [BB*NV*NV];
__device__ __align__(16) float g_WT [BB*NCAT*CC];         // WT[b][oc][c], tf32-rounded
__device__ __align__(16) float g_G  [(size_t)BB*TT*NCAT]; // G[b][t][oc]

// ---------------- helpers -----------------------------------------------------
__device__ __forceinline__ uint32_t smem_u32(const void* p) {
    uint32_t a;
    asm("{ .reg .u64 t; cvta.to.shared.u64 t, %1; cvt.u32.u64 %0, t; }"
        : "=r"(a) : "l"(p));
    return a;
}
__device__ __forceinline__ void cp16(uint32_t dst, const void* src) {
    asm volatile("cp.async.cg.shared.global [%0], [%1], 16;"
                 :: "r"(dst), "l"(src) : "memory");
}
__device__ __forceinline__ void cp_commit() {
    asm volatile("cp.async.commit_group;" ::: "memory");
}
template<int N> __device__ __forceinline__ void cp_wait() {
    asm volatile("cp.async.wait_group %0;" :: "n"(N) : "memory");
}
__device__ __forceinline__ uint32_t f2tf32(float f) {
    uint32_t u;
    asm("cvt.rna.tf32.f32 %0, %1;" : "=r"(u) : "f"(f));
    return u;
}
__device__ __forceinline__ void mma_tf32(float* d, const uint32_t* a,
                                         const uint32_t* bfr) {
    asm volatile(
        "mma.sync.aligned.m16n8k8.row.col.f32.tf32.tf32.f32 "
        "{%0,%1,%2,%3}, {%4,%5,%6,%7}, {%8,%9}, {%0,%1,%2,%3};"
        : "+f"(d[0]), "+f"(d[1]), "+f"(d[2]), "+f"(d[3])
        : "r"(a[0]), "r"(a[1]), "r"(a[2]), "r"(a[3]),
          "r"(bfr[0]), "r"(bfr[1]));
}

// ---------------- kernel 1: streaming reductions -> per-block partials --------
__global__ void __launch_bounds__(256) k1_reduce(
    const float* __restrict__ x, const float* __restrict__ W1,
    const float* __restrict__ W2, const float* __restrict__ W3)
{
    const int b  = blockIdx.y;
    const int t0 = blockIdx.x * 128;
    const int j  = threadIdx.x;
    const int f0 = (j & 3) * 4;

    __shared__ __align__(16) float sW1[128];
    __shared__ __align__(16) float sW2[16][129];

    if (j < 128) sW1[j] = W1[t0 + j];
    for (int idx = j; idx < 16*128; idx += 256) {
        int f = idx >> 7, tt = idx & 127;
        sW2[f][tt] = W2[f*TT + t0 + tt];
    }
    float w3v[4];
    #pragma unroll
    for (int d = 0; d < 4; d++) w3v[d] = W3[f0 + d];
    __syncthreads();

    float lhsacc[4] = {0,0,0,0};
    float r2acc[4]  = {0,0,0,0};
    const float4* xr = reinterpret_cast<const float4*>(
        x + (size_t)b*TT*CC + (size_t)t0*CC) + j;

    #pragma unroll 8
    for (int tt = 0; tt < 128; tt++) {
        float4 xv = xr[(size_t)tt*256];
        float s3 = xv.x*w3v[0] + xv.y*w3v[1] + xv.z*w3v[2] + xv.w*w3v[3];
        s3 += __shfl_xor_sync(0xffffffffu, s3, 1);
        s3 += __shfl_xor_sync(0xffffffffu, s3, 2);
        float w1 = sW1[tt];
        lhsacc[0] += w1*xv.x; lhsacc[1] += w1*xv.y;
        lhsacc[2] += w1*xv.z; lhsacc[3] += w1*xv.w;
        #pragma unroll
        for (int d = 0; d < 4; d++) r2acc[d] += sW2[f0+d][tt] * s3;
    }

    // channel c = 4*j + d
    size_t base = ((size_t)b*NBLK + blockIdx.x)*CC + j*4;
    *reinterpret_cast<float4*>(g_pl + base) =
        make_float4(lhsacc[0], lhsacc[1], lhsacc[2], lhsacc[3]);
    *reinterpret_cast<float4*>(g_pr + base) =
        make_float4(r2acc[0], r2acc[1], r2acc[2], r2acc[3]);
}

// ---------------- kernel 2a: reduce partials + attention matrix S -------------
__global__ void __launch_bounds__(256) k2a_S(
    const float* __restrict__ bs, const float* __restrict__ Vs)
{
    const int b = blockIdx.x;
    const int tid = threadIdx.x;
    __shared__ __align__(16) float lhs_s[NV*FF];
    __shared__ __align__(16) float R2_s [NV*FF];
    __shared__ __align__(16) float P_s  [NV*NV];
    __shared__ __align__(16) float S0_s [NV*NV];

    {
        const float4* pl = reinterpret_cast<const float4*>(g_pl) + (size_t)b*NBLK*256;
        const float4* pr = reinterpret_cast<const float4*>(g_pr) + (size_t)b*NBLK*256;
        float4 al = make_float4(0,0,0,0), ar = make_float4(0,0,0,0);
        #pragma unroll 8
        for (int blk = 0; blk < NBLK; blk++) {
            float4 v = pl[blk*256 + tid];
            al.x += v.x; al.y += v.y; al.z += v.z; al.w += v.w;
            float4 w = pr[blk*256 + tid];
            ar.x += w.x; ar.y += w.y; ar.z += w.z; ar.w += w.w;
        }
        *reinterpret_cast<float4*>(lhs_s + tid*4) = al;
        *reinterpret_cast<float4*>(R2_s  + tid*4) = ar;
    }
    __syncthreads();

    for (int i = tid; i < NV*NV; i += 256) {
        int m = i >> 6, k = i & 63;
        float acc = 0.f;
        #pragma unroll
        for (int f = 0; f < FF; f++) acc += lhs_s[m*FF+f] * R2_s[k*FF+f];
        acc += bs[i];
        P_s[i] = 1.f / (1.f + expf(-acc));
    }
    __syncthreads();

    for (int i = tid; i < NV*NV; i += 256) {
        int nn = i >> 6, k = i & 63;
        float acc = 0.f;
        #pragma unroll 8
        for (int m = 0; m < NV; m++) acc += Vs[nn*NV+m] * P_s[m*NV+k];
        S0_s[i] = acc;
    }
    __syncthreads();

    if (tid < NV) {
        const int k = tid;
        float mx = -1e30f;
        for (int nn = 0; nn < NV; nn++) mx = fmaxf(mx, S0_s[nn*NV+k]);
        float sum = 0.f;
        for (int nn = 0; nn < NV; nn++) sum += expf(S0_s[nn*NV+k] - mx);
        float inv = 1.f / sum;
        for (int nn = 0; nn < NV; nn++)
            g_S[b*NV*NV + nn*NV + k] = expf(S0_s[nn*NV+k] - mx) * inv;
    }
}

// ---------------- kernel 2b: WT, grid (O, B), coalesced conv_w ----------------
__global__ void __launch_bounds__(256) k2b_wt(
    const float* __restrict__ adj, const float* __restrict__ conv_w)
{
    const int o = blockIdx.x, b = blockIdx.y;
    const int tid = threadIdx.x;
    __shared__ __align__(16) float cws[CC*3];      // conv_w[o][c][tap], 12 KB
    __shared__ __align__(16) float SdT[NV*65];     // [n][m], pad-65

    for (int i = tid; i < CC*3; i += 256)
        cws[i] = conv_w[(size_t)o*CC*3 + i];
    for (int i = tid; i < NV*NV; i += 256) {
        int m = i >> 6, nn = i & 63;
        SdT[nn*65 + m] = g_S[b*NV*NV + i] * adj[nn*NV + nn];
    }
    __syncthreads();

    const int c0 = tid * 4;
    const int m = c0 >> 4, f0 = c0 & 15;
    float acc[3][4];
    #pragma unroll
    for (int t = 0; t < 3; t++)
        #pragma unroll
        for (int j = 0; j < 4; j++) acc[t][j] = 0.f;

    #pragma unroll 4
    for (int n = 0; n < NV; n++) {
        float s = SdT[n*65 + m];
        const float4* cw4 = reinterpret_cast<const float4*>(
            cws + (n*FF + f0)*3);
        float4 w0 = cw4[0], w1 = cw4[1], w2 = cw4[2];
        acc[0][0] += s*w0.x; acc[1][0] += s*w0.y; acc[2][0] += s*w0.z;
        acc[0][1] += s*w0.w; acc[1][1] += s*w1.x; acc[2][1] += s*w1.y;
        acc[0][2] += s*w1.z; acc[1][2] += s*w1.w; acc[2][2] += s*w2.x;
        acc[0][3] += s*w2.y; acc[1][3] += s*w2.z; acc[2][3] += s*w2.w;
    }

    #pragma unroll
    for (int t = 0; t < 3; t++) {
        float4 v = make_float4(
            __uint_as_float(f2tf32(acc[t][0])), __uint_as_float(f2tf32(acc[t][1])),
            __uint_as_float(f2tf32(acc[t][2])), __uint_as_float(f2tf32(acc[t][3])));
        *reinterpret_cast<float4*>(
            g_WT + ((size_t)b*NCAT + t*OO + o)*CC + c0) = v;
    }
}

// ---------------- kernel 3: G = x @ WT^T via mma.sync tf32, 3-stage pipe ------
// MT=64 per CTA -> grid 512, ~3.5 CTA/SM, occ ~21%. Warp tile 16x96.
#define MT   64
#define KC   32
#define NSTG (CC/KC)          // 32
#define ROWP 36               // floats per smem row (9 float4)
#define XSZ  (MT*ROWP*4)      // 9216 B
#define WSZ  (NCAT*ROWP*4)    // 13824 B
#define BUFSZ (XSZ + WSZ)     // 23040 B
#define SMEM_K3 (3*BUFSZ)     // 69120 B

__global__ void __launch_bounds__(128) k3_mma(const float* __restrict__ x)
{
    extern __shared__ __align__(16) float smemf[];
    const uint32_t sb = smem_u32(smemf);
    const int tid  = threadIdx.x;
    const int wid  = tid >> 5, lane = tid & 31;
    const int g    = lane >> 2;           // 0..7
    const int t4   = lane & 3;            // 0..3
    const int b    = blockIdx.y;
    const size_t m0 = (size_t)blockIdx.x * MT;

    const char* xg = (const char*)(x + ((size_t)b*TT + m0)*CC);
    const char* wg = (const char*)(g_WT + (size_t)b*NCAT*CC);

    float acc[12][4];
    #pragma unroll
    for (int j = 0; j < 12; j++)
        #pragma unroll
        for (int d = 0; d < 4; d++) acc[j][d] = 0.f;

    #define LOAD_STAGE(s) do {                                                  \
        uint32_t bd_ = sb + ((s) % 3) * BUFSZ;                                  \
        int c0b = (s)*KC*4;                                                     \
        _Pragma("unroll")                                                       \
        for (int i = 0; i < 4; i++) {   /* 64 x-rows: 512 f4 */                 \
            int idx = tid + i*128; int row = idx >> 3, q = idx & 7;             \
            cp16(bd_ + row*(ROWP*4) + q*16, xg + (size_t)row*CC*4 + c0b + q*16);\
        }                                                                       \
        _Pragma("unroll")                                                       \
        for (int i = 0; i < 6; i++) {   /* 96 w-rows: 768 f4 */                 \
            int idx = tid + i*128; int row = idx >> 3, q = idx & 7;             \
            cp16(bd_ + XSZ + row*(ROWP*4) + q*16,                               \
                 wg + (size_t)row*CC*4 + c0b + q*16);                           \
        }                                                                       \
        cp_commit();                                                            \
    } while (0)

    LOAD_STAGE(0);
    LOAD_STAGE(1);

    const int wr = wid * 16;
    const int f4q = t4 * 2;

    for (int s = 0; s < NSTG; s++) {
        if (s + 1 < NSTG) cp_wait<1>();
        else              cp_wait<0>();
        __syncthreads();
        if (s + 2 < NSTG) LOAD_STAGE(s + 2);

        const float4* xs4 = reinterpret_cast<const float4*>(
            (const char*)smemf + (s % 3) * BUFSZ);
        const float4* ws4 = reinterpret_cast<const float4*>(
            (const char*)smemf + (s % 3) * BUFSZ + XSZ);

        // A fragments: 16 rows (one m16 tile), phys cols [8*t4, 8*t4+8)
        uint32_t ae[2][8];
        #pragma unroll
        for (int r = 0; r < 2; r++) {
            int row = wr + r*8 + g;
            float4 lo = xs4[row*9 + f4q];
            float4 hi = xs4[row*9 + f4q + 1];
            ae[r][0] = f2tf32(lo.x); ae[r][1] = f2tf32(lo.y);
            ae[r][2] = f2tf32(lo.z); ae[r][3] = f2tf32(lo.w);
            ae[r][4] = f2tf32(hi.x); ae[r][5] = f2tf32(hi.y);
            ae[r][6] = f2tf32(hi.z); ae[r][7] = f2tf32(hi.w);
        }

        #pragma unroll
        for (int j = 0; j < 12; j++) {
            int nr = 8*j + g;
            float4 blo = ws4[nr*9 + f4q];
            float4 bhi = ws4[nr*9 + f4q + 1];
            uint32_t be[8] = {
                __float_as_uint(blo.x), __float_as_uint(blo.y),
                __float_as_uint(blo.z), __float_as_uint(blo.w),
                __float_as_uint(bhi.x), __float_as_uint(bhi.y),
                __float_as_uint(bhi.z), __float_as_uint(bhi.w) };
            #pragma unroll
            for (int ks = 0; ks < 4; ks++) {
                uint32_t b2[2] = { be[2*ks], be[2*ks+1] };
                uint32_t a4[4] = { ae[0][2*ks], ae[1][2*ks],
                                   ae[0][2*ks+1], ae[1][2*ks+1] };
                mma_tf32(acc[j], a4, b2);
            }
        }
    }

    // epilogue: rows wr+g and wr+g+8, cols 8j + 2*t4 (+1)
    float* gr = g_G + ((size_t)b*TT + m0 + (size_t)wid*16)*NCAT;
    #pragma unroll
    for (int j = 0; j < 12; j++) {
        int col = 8*j + 2*t4;
        *reinterpret_cast<float2*>(gr + (size_t)g*NCAT + col) =
            make_float2(acc[j][0], acc[j][1]);
        *reinterpret_cast<float2*>(gr + (size_t)(g+8)*NCAT + col) =
            make_float2(acc[j][2], acc[j][3]);
    }
}

// ---------------- kernel 4: out[t,o] = G[t-1,o] + G[t,32+o] + G[t+1,64+o] -----
__global__ void __launch_bounds__(256) k4_combine(float* __restrict__ out)
{
    const int b = blockIdx.y;
    const int idx = blockIdx.x*256 + threadIdx.x;   // over TT*8
    const int t = idx >> 3, q = idx & 7;
    const float* Gb = g_G + (size_t)b*TT*NCAT;

    float4 acc = make_float4(0.f, 0.f, 0.f, 0.f);
    if (t > 0) {
        float4 v = *reinterpret_cast<const float4*>(Gb + (size_t)(t-1)*NCAT + q*4);
        acc.x += v.x; acc.y += v.y; acc.z += v.z; acc.w += v.w;
    }
    {
        float4 v = *reinterpret_cast<const float4*>(Gb + (size_t)t*NCAT + 32 + q*4);
        acc.x += v.x; acc.y += v.y; acc.z += v.z; acc.w += v.w;
    }
    if (t < TT-1) {
        float4 v = *reinterpret_cast<const float4*>(Gb + (size_t)(t+1)*NCAT + 64 + q*4);
        acc.x += v.x; acc.y += v.y; acc.z += v.z; acc.w += v.w;
    }
    *reinterpret_cast<float4*>(out + ((size_t)b*TT + t)*OO + q*4) = acc;
}

// ---------------- launch ------------------------------------------------------
extern "C" void kernel_launch(void* const* d_in, const int* in_sizes, int n_in,
                              void* d_out, int out_size)
{
    const float* x      = (const float*)d_in[0];
    const float* adj    = (const float*)d_in[1];
    const float* W1     = (const float*)d_in[2];
    const float* W2     = (const float*)d_in[3];
    const float* W3     = (const float*)d_in[4];
    const float* bs     = (const float*)d_in[5];
    const float* Vs     = (const float*)d_in[6];
    const float* conv_w = (const float*)d_in[7];
    float* out = (float*)d_out;

    cudaFuncSetAttribute(k3_mma, cudaFuncAttributeMaxDynamicSharedMemorySize,
                         SMEM_K3);

    k1_reduce<<<dim3(NBLK, BB), 256>>>(x, W1, W2, W3);   // idx 0
    k2a_S<<<BB, 256>>>(bs, Vs);                          // idx 1
    k2b_wt<<<dim3(OO, BB), 256>>>(adj, conv_w);          // idx 2
    k3_mma<<<dim3(TT/MT, BB), 128, SMEM_K3>>>(x);        // idx 3  <- ncu window
    k4_combine<<<dim3(TT*8/256, BB), 256>>>(out);        // idx 4
}

// round 13
// speedup vs baseline: 1.1293x; 1.0655x over previous
#include <cuda_runtime.h>
#include <math.h>
#include <stdint.h>

#define BB 4
#define TT 8192
#define NV 64
#define FF 16
#define CC 1024   // NV*FF
#define OO 32
#define NCAT 96   // 3 taps * 32 outputs
#define NBLK 128  // k1 blocks per batch
#define K1T  64   // t-rows per k1 block

// ---------------- scratch (static device globals; no allocation) -------------
__device__ __align__(16) float g_pl [BB*NBLK*CC];         // k1 partial lhs
__device__ __align__(16) float g_pr [BB*NBLK*CC];         // k1 partial r2
__device__ __align__(16) float g_S  [BB*NV*NV];
__device__ __align__(16) float g_WT [BB*NCAT*CC];         // WT[b][oc][c], tf32-rounded
__device__ __align__(16) float g_G  [(size_t)BB*TT*NCAT]; // G[b][t][oc]

// ---------------- helpers -----------------------------------------------------
__device__ __forceinline__ uint32_t smem_u32(const void* p) {
    uint32_t a;
    asm("{ .reg .u64 t; cvta.to.shared.u64 t, %1; cvt.u32.u64 %0, t; }"
        : "=r"(a) : "l"(p));
    return a;
}
__device__ __forceinline__ void cp16(uint32_t dst, const void* src) {
    asm volatile("cp.async.cg.shared.global [%0], [%1], 16;"
                 :: "r"(dst), "l"(src) : "memory");
}
__device__ __forceinline__ void cp_commit() {
    asm volatile("cp.async.commit_group;" ::: "memory");
}
template<int N> __device__ __forceinline__ void cp_wait() {
    asm volatile("cp.async.wait_group %0;" :: "n"(N) : "memory");
}
__device__ __forceinline__ uint32_t f2tf32(float f) {
    uint32_t u;
    asm("cvt.rna.tf32.f32 %0, %1;" : "=r"(u) : "f"(f));
    return u;
}
__device__ __forceinline__ void mma_tf32(float* d, const uint32_t* a,
                                         const uint32_t* bfr) {
    asm volatile(
        "mma.sync.aligned.m16n8k8.row.col.f32.tf32.tf32.f32 "
        "{%0,%1,%2,%3}, {%4,%5,%6,%7}, {%8,%9}, {%0,%1,%2,%3};"
        : "+f"(d[0]), "+f"(d[1]), "+f"(d[2]), "+f"(d[3])
        : "r"(a[0]), "r"(a[1]), "r"(a[2]), "r"(a[3]),
          "r"(bfr[0]), "r"(bfr[1]));
}

// ---------------- kernel 1: streaming reductions -> per-block partials --------
__global__ void __launch_bounds__(256) k1_reduce(
    const float* __restrict__ x, const float* __restrict__ W1,
    const float* __restrict__ W2, const float* __restrict__ W3)
{
    const int b  = blockIdx.y;
    const int t0 = blockIdx.x * K1T;
    const int j  = threadIdx.x;
    const int f0 = (j & 3) * 4;

    __shared__ __align__(16) float sW1[K1T];
    __shared__ __align__(16) float sW2[16][K1T+1];

    if (j < K1T) sW1[j] = W1[t0 + j];
    for (int idx = j; idx < 16*K1T; idx += 256) {
        int f = idx >> 6, tt = idx & (K1T-1);
        sW2[f][tt] = W2[f*TT + t0 + tt];
    }
    float w3v[4];
    #pragma unroll
    for (int d = 0; d < 4; d++) w3v[d] = W3[f0 + d];
    __syncthreads();

    float lhsacc[4] = {0,0,0,0};
    float r2acc[4]  = {0,0,0,0};
    const float4* xr = reinterpret_cast<const float4*>(
        x + (size_t)b*TT*CC + (size_t)t0*CC) + j;

    #pragma unroll 8
    for (int tt = 0; tt < K1T; tt++) {
        float4 xv = xr[(size_t)tt*256];
        float s3 = xv.x*w3v[0] + xv.y*w3v[1] + xv.z*w3v[2] + xv.w*w3v[3];
        s3 += __shfl_xor_sync(0xffffffffu, s3, 1);
        s3 += __shfl_xor_sync(0xffffffffu, s3, 2);
        float w1 = sW1[tt];
        lhsacc[0] += w1*xv.x; lhsacc[1] += w1*xv.y;
        lhsacc[2] += w1*xv.z; lhsacc[3] += w1*xv.w;
        #pragma unroll
        for (int d = 0; d < 4; d++) r2acc[d] += sW2[f0+d][tt] * s3;
    }

    size_t base = ((size_t)b*NBLK + blockIdx.x)*CC + j*4;
    *reinterpret_cast<float4*>(g_pl + base) =
        make_float4(lhsacc[0], lhsacc[1], lhsacc[2], lhsacc[3]);
    *reinterpret_cast<float4*>(g_pr + base) =
        make_float4(r2acc[0], r2acc[1], r2acc[2], r2acc[3]);
}

// ---------------- kernel 2a: reduce partials + attention matrix S -------------
__global__ void __launch_bounds__(256) k2a_S(
    const float* __restrict__ bs, const float* __restrict__ Vs)
{
    const int b = blockIdx.x;
    const int tid = threadIdx.x;
    __shared__ __align__(16) float lhs_s[NV*FF];
    __shared__ __align__(16) float R2_s [NV*FF];
    __shared__ __align__(16) float P_s  [NV*NV];
    __shared__ __align__(16) float S0_s [NV*NV];

    {
        const float4* pl = reinterpret_cast<const float4*>(g_pl) + (size_t)b*NBLK*256;
        const float4* pr = reinterpret_cast<const float4*>(g_pr) + (size_t)b*NBLK*256;
        float4 al = make_float4(0,0,0,0), ar = make_float4(0,0,0,0);
        #pragma unroll 8
        for (int blk = 0; blk < NBLK; blk++) {
            float4 v = pl[blk*256 + tid];
            al.x += v.x; al.y += v.y; al.z += v.z; al.w += v.w;
            float4 w = pr[blk*256 + tid];
            ar.x += w.x; ar.y += w.y; ar.z += w.z; ar.w += w.w;
        }
        *reinterpret_cast<float4*>(lhs_s + tid*4) = al;
        *reinterpret_cast<float4*>(R2_s  + tid*4) = ar;
    }
    __syncthreads();

    for (int i = tid; i < NV*NV; i += 256) {
        int m = i >> 6, k = i & 63;
        float acc = 0.f;
        #pragma unroll
        for (int f = 0; f < FF; f++) acc += lhs_s[m*FF+f] * R2_s[k*FF+f];
        acc += bs[i];
        P_s[i] = 1.f / (1.f + expf(-acc));
    }
    __syncthreads();

    for (int i = tid; i < NV*NV; i += 256) {
        int nn = i >> 6, k = i & 63;
        float acc = 0.f;
        #pragma unroll 8
        for (int m = 0; m < NV; m++) acc += Vs[nn*NV+m] * P_s[m*NV+k];
        S0_s[i] = acc;
    }
    __syncthreads();

    if (tid < NV) {
        const int k = tid;
        float mx = -1e30f;
        for (int nn = 0; nn < NV; nn++) mx = fmaxf(mx, S0_s[nn*NV+k]);
        float sum = 0.f;
        for (int nn = 0; nn < NV; nn++) sum += expf(S0_s[nn*NV+k] - mx);
        float inv = 1.f / sum;
        for (int nn = 0; nn < NV; nn++)
            g_S[b*NV*NV + nn*NV + k] = expf(S0_s[nn*NV+k] - mx) * inv;
    }
}

// ---------------- kernel 2b: WT, grid (O, B), coalesced conv_w ----------------
__global__ void __launch_bounds__(256) k2b_wt(
    const float* __restrict__ adj, const float* __restrict__ conv_w)
{
    const int o = blockIdx.x, b = blockIdx.y;
    const int tid = threadIdx.x;
    __shared__ __align__(16) float cws[CC*3];      // conv_w[o][c][tap], 12 KB
    __shared__ __align__(16) float SdT[NV*65];     // [n][m], pad-65

    for (int i = tid; i < CC*3; i += 256)
        cws[i] = conv_w[(size_t)o*CC*3 + i];
    for (int i = tid; i < NV*NV; i += 256) {
        int m = i >> 6, nn = i & 63;
        SdT[nn*65 + m] = g_S[b*NV*NV + i] * adj[nn*NV + nn];
    }
    __syncthreads();

    const int c0 = tid * 4;
    const int m = c0 >> 4, f0 = c0 & 15;
    float acc[3][4];
    #pragma unroll
    for (int t = 0; t < 3; t++)
        #pragma unroll
        for (int j = 0; j < 4; j++) acc[t][j] = 0.f;

    #pragma unroll 4
    for (int n = 0; n < NV; n++) {
        float s = SdT[n*65 + m];
        const float4* cw4 = reinterpret_cast<const float4*>(
            cws + (n*FF + f0)*3);
        float4 w0 = cw4[0], w1 = cw4[1], w2 = cw4[2];
        acc[0][0] += s*w0.x; acc[1][0] += s*w0.y; acc[2][0] += s*w0.z;
        acc[0][1] += s*w0.w; acc[1][1] += s*w1.x; acc[2][1] += s*w1.y;
        acc[0][2] += s*w1.z; acc[1][2] += s*w1.w; acc[2][2] += s*w2.x;
        acc[0][3] += s*w2.y; acc[1][3] += s*w2.z; acc[2][3] += s*w2.w;
    }

    #pragma unroll
    for (int t = 0; t < 3; t++) {
        float4 v = make_float4(
            __uint_as_float(f2tf32(acc[t][0])), __uint_as_float(f2tf32(acc[t][1])),
            __uint_as_float(f2tf32(acc[t][2])), __uint_as_float(f2tf32(acc[t][3])));
        *reinterpret_cast<float4*>(
            g_WT + ((size_t)b*NCAT + t*OO + o)*CC + c0) = v;
    }
}

// ---------------- kernel 3: G = x @ WT^T, mma.sync tf32, 2-stage pipe ---------
// MT=64, grid 512, smem 46KB -> 4 CTA/SM -> capacity 592 >= 512 = SINGLE WAVE.
#define MT   64
#define KC   32
#define NSTG (CC/KC)          // 32
#define ROWP 36               // floats per smem row (9 float4)
#define XSZ  (MT*ROWP*4)      // 9216 B
#define WSZ  (NCAT*ROWP*4)    // 13824 B
#define BUFSZ (XSZ + WSZ)     // 23040 B
#define SMEM_K3 (2*BUFSZ)     // 46080 B

__global__ void __launch_bounds__(128) k3_mma(const float* __restrict__ x)
{
    extern __shared__ __align__(16) float smemf[];
    const uint32_t sb = smem_u32(smemf);
    const int tid  = threadIdx.x;
    const int wid  = tid >> 5, lane = tid & 31;
    const int g    = lane >> 2;           // 0..7
    const int t4   = lane & 3;            // 0..3
    const int b    = blockIdx.y;
    const size_t m0 = (size_t)blockIdx.x * MT;

    const char* xg = (const char*)(x + ((size_t)b*TT + m0)*CC);
    const char* wg = (const char*)(g_WT + (size_t)b*NCAT*CC);

    float acc[12][4];
    #pragma unroll
    for (int j = 0; j < 12; j++)
        #pragma unroll
        for (int d = 0; d < 4; d++) acc[j][d] = 0.f;

    #define LOAD_STAGE(s) do {                                                  \
        uint32_t bd_ = sb + ((s) & 1) * BUFSZ;                                  \
        int c0b = (s)*KC*4;                                                     \
        _Pragma("unroll")                                                       \
        for (int i = 0; i < 4; i++) {   /* 64 x-rows: 512 f4 */                 \
            int idx = tid + i*128; int row = idx >> 3, q = idx & 7;             \
            cp16(bd_ + row*(ROWP*4) + q*16, xg + (size_t)row*CC*4 + c0b + q*16);\
        }                                                                       \
        _Pragma("unroll")                                                       \
        for (int i = 0; i < 6; i++) {   /* 96 w-rows: 768 f4 */                 \
            int idx = tid + i*128; int row = idx >> 3, q = idx & 7;             \
            cp16(bd_ + XSZ + row*(ROWP*4) + q*16,                               \
                 wg + (size_t)row*CC*4 + c0b + q*16);                           \
        }                                                                       \
        cp_commit();                                                            \
    } while (0)

    LOAD_STAGE(0);

    const int wr = wid * 16;
    const int f4q = t4 * 2;

    for (int s = 0; s < NSTG; s++) {
        cp_wait<0>();          // stage s data complete
        __syncthreads();       // visible; all warps past compute(s-1)
        if (s + 1 < NSTG) LOAD_STAGE(s + 1);   // other buffer now free

        const float4* xs4 = reinterpret_cast<const float4*>(
            (const char*)smemf + (s & 1) * BUFSZ);
        const float4* ws4 = reinterpret_cast<const float4*>(
            (const char*)smemf + (s & 1) * BUFSZ + XSZ);

        uint32_t ae[2][8];
        #pragma unroll
        for (int r = 0; r < 2; r++) {
            int row = wr + r*8 + g;
            float4 lo = xs4[row*9 + f4q];
            float4 hi = xs4[row*9 + f4q + 1];
            ae[r][0] = f2tf32(lo.x); ae[r][1] = f2tf32(lo.y);
            ae[r][2] = f2tf32(lo.z); ae[r][3] = f2tf32(lo.w);
            ae[r][4] = f2tf32(hi.x); ae[r][5] = f2tf32(hi.y);
            ae[r][6] = f2tf32(hi.z); ae[r][7] = f2tf32(hi.w);
        }

        #pragma unroll
        for (int j = 0; j < 12; j++) {
            int nr = 8*j + g;
            float4 blo = ws4[nr*9 + f4q];
            float4 bhi = ws4[nr*9 + f4q + 1];
            uint32_t be[8] = {
                __float_as_uint(blo.x), __float_as_uint(blo.y),
                __float_as_uint(blo.z), __float_as_uint(blo.w),
                __float_as_uint(bhi.x), __float_as_uint(bhi.y),
                __float_as_uint(bhi.z), __float_as_uint(bhi.w) };
            #pragma unroll
            for (int ks = 0; ks < 4; ks++) {
                uint32_t b2[2] = { be[2*ks], be[2*ks+1] };
                uint32_t a4[4] = { ae[0][2*ks], ae[1][2*ks],
                                   ae[0][2*ks+1], ae[1][2*ks+1] };
                mma_tf32(acc[j], a4, b2);
            }
        }
    }

    float* gr = g_G + ((size_t)b*TT + m0 + (size_t)wid*16)*NCAT;
    #pragma unroll
    for (int j = 0; j < 12; j++) {
        int col = 8*j + 2*t4;
        *reinterpret_cast<float2*>(gr + (size_t)g*NCAT + col) =
            make_float2(acc[j][0], acc[j][1]);
        *reinterpret_cast<float2*>(gr + (size_t)(g+8)*NCAT + col) =
            make_float2(acc[j][2], acc[j][3]);
    }
}

// ---------------- kernel 4: out[t,o] = G[t-1,o] + G[t,32+o] + G[t+1,64+o] -----
__global__ void __launch_bounds__(256) k4_combine(float* __restrict__ out)
{
    const int b = blockIdx.y;
    const int idx = blockIdx.x*256 + threadIdx.x;   // over TT*8
    const int t = idx >> 3, q = idx & 7;
    const float* Gb = g_G + (size_t)b*TT*NCAT;

    float4 acc = make_float4(0.f, 0.f, 0.f, 0.f);
    if (t > 0) {
        float4 v = *reinterpret_cast<const float4*>(Gb + (size_t)(t-1)*NCAT + q*4);
        acc.x += v.x; acc.y += v.y; acc.z += v.z; acc.w += v.w;
    }
    {
        float4 v = *reinterpret_cast<const float4*>(Gb + (size_t)t*NCAT + 32 + q*4);
        acc.x += v.x; acc.y += v.y; acc.z += v.z; acc.w += v.w;
    }
    if (t < TT-1) {
        float4 v = *reinterpret_cast<const float4*>(Gb + (size_t)(t+1)*NCAT + 64 + q*4);
        acc.x += v.x; acc.y += v.y; acc.z += v.z; acc.w += v.w;
    }
    *reinterpret_cast<float4*>(out + ((size_t)b*TT + t)*OO + q*4) = acc;
}

// ---------------- launch ------------------------------------------------------
extern "C" void kernel_launch(void* const* d_in, const int* in_sizes, int n_in,
                              void* d_out, int out_size)
{
    const float* x      = (const float*)d_in[0];
    const float* adj    = (const float*)d_in[1];
    const float* W1     = (const float*)d_in[2];
    const float* W2     = (const float*)d_in[3];
    const float* W3     = (const float*)d_in[4];
    const float* bs     = (const float*)d_in[5];
    const float* Vs     = (const float*)d_in[6];
    const float* conv_w = (const float*)d_in[7];
    float* out = (float*)d_out;

    cudaFuncSetAttribute(k3_mma, cudaFuncAttributeMaxDynamicSharedMemorySize,
                         SMEM_K3);

    k1_reduce<<<dim3(NBLK, BB), 256>>>(x, W1, W2, W3);   // idx 0
    k2a_S<<<BB, 256>>>(bs, Vs);                          // idx 1
    k2b_wt<<<dim3(OO, BB), 256>>>(adj, conv_w);          // idx 2
    k3_mma<<<dim3(TT/MT, BB), 128, SMEM_K3>>>(x);        // idx 3  <- ncu window
    k4_combine<<<dim3(TT*8/256, BB), 256>>>(out);        // idx 4
}

// round 14
// speedup vs baseline: 1.2316x; 1.0906x over previous
#include <cuda_runtime.h>
#include <cuda_fp16.h>
#include <math.h>
#include <stdint.h>

#define BB 4
#define TT 8192
#define NV 64
#define FF 16
#define CC 1024   // NV*FF
#define OO 32
#define NCAT 96   // 3 taps * 32 outputs
#define NBLK 128  // k1 blocks per batch
#define K1T  64   // t-rows per k1 block

// ---------------- scratch (static device globals; no allocation) -------------
__device__ __align__(16) float  g_pl [BB*NBLK*CC];          // k1 partial lhs
__device__ __align__(16) float  g_pr [BB*NBLK*CC];          // k1 partial r2
__device__ __align__(16) float  g_S  [BB*NV*NV];
__device__ __align__(16) __half g_x16[(size_t)BB*TT*CC];    // fp16 copy of x
__device__ __align__(16) __half g_wt16[BB*NCAT*CC];         // WT[b][oc][c] fp16
__device__ __align__(16) float  g_G  [(size_t)BB*TT*NCAT];  // G[b][t][oc]

// ---------------- helpers -----------------------------------------------------
__device__ __forceinline__ uint32_t smem_u32(const void* p) {
    uint32_t a;
    asm("{ .reg .u64 t; cvta.to.shared.u64 t, %1; cvt.u32.u64 %0, t; }"
        : "=r"(a) : "l"(p));
    return a;
}
__device__ __forceinline__ void cp16(uint32_t dst, const void* src) {
    asm volatile("cp.async.cg.shared.global [%0], [%1], 16;"
                 :: "r"(dst), "l"(src) : "memory");
}
__device__ __forceinline__ void cp_commit() {
    asm volatile("cp.async.commit_group;" ::: "memory");
}
template<int N> __device__ __forceinline__ void cp_wait() {
    asm volatile("cp.async.wait_group %0;" :: "n"(N) : "memory");
}
// fp16 MMA m16n8k16, fp32 accumulate
__device__ __forceinline__ void mma_f16(float* d, uint32_t a0, uint32_t a1,
                                        uint32_t a2, uint32_t a3,
                                        uint32_t b0, uint32_t b1) {
    asm volatile(
        "mma.sync.aligned.m16n8k16.row.col.f32.f16.f16.f32 "
        "{%0,%1,%2,%3}, {%4,%5,%6,%7}, {%8,%9}, {%0,%1,%2,%3};"
        : "+f"(d[0]), "+f"(d[1]), "+f"(d[2]), "+f"(d[3])
        : "r"(a0), "r"(a1), "r"(a2), "r"(a3), "r"(b0), "r"(b1));
}

// ---------------- kernel 1: reductions + fp16 transcode -----------------------
__global__ void __launch_bounds__(256) k1_reduce(
    const float* __restrict__ x, const float* __restrict__ W1,
    const float* __restrict__ W2, const float* __restrict__ W3)
{
    const int b  = blockIdx.y;
    const int t0 = blockIdx.x * K1T;
    const int j  = threadIdx.x;
    const int f0 = (j & 3) * 4;

    __shared__ __align__(16) float sW1[K1T];
    __shared__ __align__(16) float sW2[16][K1T+1];

    if (j < K1T) sW1[j] = W1[t0 + j];
    for (int idx = j; idx < 16*K1T; idx += 256) {
        int f = idx >> 6, tt = idx & (K1T-1);
        sW2[f][tt] = W2[f*TT + t0 + tt];
    }
    float w3v[4];
    #pragma unroll
    for (int d = 0; d < 4; d++) w3v[d] = W3[f0 + d];
    __syncthreads();

    float lhsacc[4] = {0,0,0,0};
    float r2acc[4]  = {0,0,0,0};
    const float4* xr = reinterpret_cast<const float4*>(
        x + (size_t)b*TT*CC + (size_t)t0*CC) + j;
    __half* x16r = g_x16 + ((size_t)b*TT + t0)*CC + j*4;

    #pragma unroll 8
    for (int tt = 0; tt < K1T; tt++) {
        float4 xv = xr[(size_t)tt*256];
        // fp16 transcode (8B store, 8B-aligned)
        __half2 h0 = __floats2half2_rn(xv.x, xv.y);
        __half2 h1 = __floats2half2_rn(xv.z, xv.w);
        uint2 pk;
        pk.x = *reinterpret_cast<uint32_t*>(&h0);
        pk.y = *reinterpret_cast<uint32_t*>(&h1);
        *reinterpret_cast<uint2*>(x16r + (size_t)tt*CC) = pk;

        float s3 = xv.x*w3v[0] + xv.y*w3v[1] + xv.z*w3v[2] + xv.w*w3v[3];
        s3 += __shfl_xor_sync(0xffffffffu, s3, 1);
        s3 += __shfl_xor_sync(0xffffffffu, s3, 2);
        float w1 = sW1[tt];
        lhsacc[0] += w1*xv.x; lhsacc[1] += w1*xv.y;
        lhsacc[2] += w1*xv.z; lhsacc[3] += w1*xv.w;
        #pragma unroll
        for (int d = 0; d < 4; d++) r2acc[d] += sW2[f0+d][tt] * s3;
    }

    size_t base = ((size_t)b*NBLK + blockIdx.x)*CC + j*4;
    *reinterpret_cast<float4*>(g_pl + base) =
        make_float4(lhsacc[0], lhsacc[1], lhsacc[2], lhsacc[3]);
    *reinterpret_cast<float4*>(g_pr + base) =
        make_float4(r2acc[0], r2acc[1], r2acc[2], r2acc[3]);
}

// ---------------- kernel 2a: reduce partials + attention matrix S -------------
__global__ void __launch_bounds__(256) k2a_S(
    const float* __restrict__ bs, const float* __restrict__ Vs)
{
    const int b = blockIdx.x;
    const int tid = threadIdx.x;
    __shared__ __align__(16) float lhs_s[NV*FF];
    __shared__ __align__(16) float R2_s [NV*FF];
    __shared__ __align__(16) float P_s  [NV*NV];
    __shared__ __align__(16) float S0_s [NV*NV];

    {
        const float4* pl = reinterpret_cast<const float4*>(g_pl) + (size_t)b*NBLK*256;
        const float4* pr = reinterpret_cast<const float4*>(g_pr) + (size_t)b*NBLK*256;
        float4 al = make_float4(0,0,0,0), ar = make_float4(0,0,0,0);
        #pragma unroll 8
        for (int blk = 0; blk < NBLK; blk++) {
            float4 v = pl[blk*256 + tid];
            al.x += v.x; al.y += v.y; al.z += v.z; al.w += v.w;
            float4 w = pr[blk*256 + tid];
            ar.x += w.x; ar.y += w.y; ar.z += w.z; ar.w += w.w;
        }
        *reinterpret_cast<float4*>(lhs_s + tid*4) = al;
        *reinterpret_cast<float4*>(R2_s  + tid*4) = ar;
    }
    __syncthreads();

    for (int i = tid; i < NV*NV; i += 256) {
        int m = i >> 6, k = i & 63;
        float acc = 0.f;
        #pragma unroll
        for (int f = 0; f < FF; f++) acc += lhs_s[m*FF+f] * R2_s[k*FF+f];
        acc += bs[i];
        P_s[i] = 1.f / (1.f + expf(-acc));
    }
    __syncthreads();

    for (int i = tid; i < NV*NV; i += 256) {
        int nn = i >> 6, k = i & 63;
        float acc = 0.f;
        #pragma unroll 8
        for (int m = 0; m < NV; m++) acc += Vs[nn*NV+m] * P_s[m*NV+k];
        S0_s[i] = acc;
    }
    __syncthreads();

    if (tid < NV) {
        const int k = tid;
        float mx = -1e30f;
        for (int nn = 0; nn < NV; nn++) mx = fmaxf(mx, S0_s[nn*NV+k]);
        float sum = 0.f;
        for (int nn = 0; nn < NV; nn++) sum += expf(S0_s[nn*NV+k] - mx);
        float inv = 1.f / sum;
        for (int nn = 0; nn < NV; nn++)
            g_S[b*NV*NV + nn*NV + k] = expf(S0_s[nn*NV+k] - mx) * inv;
    }
}

// ---------------- kernel 2b: WT fp16, grid (O, B) -----------------------------
__global__ void __launch_bounds__(256) k2b_wt(
    const float* __restrict__ adj, const float* __restrict__ conv_w)
{
    const int o = blockIdx.x, b = blockIdx.y;
    const int tid = threadIdx.x;
    __shared__ __align__(16) float cws[CC*3];      // conv_w[o][c][tap], 12 KB
    __shared__ __align__(16) float SdT[NV*65];     // [n][m], pad-65

    for (int i = tid; i < CC*3; i += 256)
        cws[i] = conv_w[(size_t)o*CC*3 + i];
    for (int i = tid; i < NV*NV; i += 256) {
        int m = i >> 6, nn = i & 63;
        SdT[nn*65 + m] = g_S[b*NV*NV + i] * adj[nn*NV + nn];
    }
    __syncthreads();

    const int c0 = tid * 4;
    const int m = c0 >> 4, f0 = c0 & 15;
    float acc[3][4];
    #pragma unroll
    for (int t = 0; t < 3; t++)
        #pragma unroll
        for (int j = 0; j < 4; j++) acc[t][j] = 0.f;

    #pragma unroll 4
    for (int n = 0; n < NV; n++) {
        float s = SdT[n*65 + m];
        const float4* cw4 = reinterpret_cast<const float4*>(
            cws + (n*FF + f0)*3);
        float4 w0 = cw4[0], w1 = cw4[1], w2 = cw4[2];
        acc[0][0] += s*w0.x; acc[1][0] += s*w0.y; acc[2][0] += s*w0.z;
        acc[0][1] += s*w0.w; acc[1][1] += s*w1.x; acc[2][1] += s*w1.y;
        acc[0][2] += s*w1.z; acc[1][2] += s*w1.w; acc[2][2] += s*w2.x;
        acc[0][3] += s*w2.y; acc[1][3] += s*w2.z; acc[2][3] += s*w2.w;
    }

    #pragma unroll
    for (int t = 0; t < 3; t++) {
        __half2 h0 = __floats2half2_rn(acc[t][0], acc[t][1]);
        __half2 h1 = __floats2half2_rn(acc[t][2], acc[t][3]);
        uint2 pk;
        pk.x = *reinterpret_cast<uint32_t*>(&h0);
        pk.y = *reinterpret_cast<uint32_t*>(&h1);
        *reinterpret_cast<uint2*>(
            g_wt16 + ((size_t)b*NCAT + t*OO + o)*CC + c0) = pk;
    }
}

// ---------------- kernel 3: G = x16 @ WT16^T, mma.sync fp16 m16n8k16 ----------
// MT=64, KC=64 halves/stage (128B rows, padded to 144B = 9 chunks -> LDS.128
// conflict-free), NSTG=16, 2-stage pipe, smem 46KB -> 4 CTA/SM, single wave.
// Free k-perm: thread t4 owns phys cols [16t4, 16t4+16) -> 2 LDS.128/row;
// half2 reg h[2ks] = lo pair of kstep ks, h[2ks+1] = hi pair.
#define MT    64
#define KC16  64              // halves per stage
#define NSTG  (CC/KC16)       // 16
#define ROWB  144             // bytes per smem row (9 x 16B chunks)
#define XSZ   (MT*ROWB)       // 9216 B
#define WSZ   (NCAT*ROWB)     // 13824 B
#define BUFSZ (XSZ + WSZ)     // 23040 B
#define SMEM_K3 (2*BUFSZ)     // 46080 B

__global__ void __launch_bounds__(128) k3_mma()
{
    extern __shared__ __align__(16) char smemc[];
    const uint32_t sb = smem_u32(smemc);
    const int tid  = threadIdx.x;
    const int wid  = tid >> 5, lane = tid & 31;
    const int g    = lane >> 2;           // 0..7
    const int t4   = lane & 3;            // 0..3
    const int b    = blockIdx.y;
    const size_t m0 = (size_t)blockIdx.x * MT;

    const char* xg = (const char*)(g_x16 + ((size_t)b*TT + m0)*CC);
    const char* wg = (const char*)(g_wt16 + (size_t)b*NCAT*CC);

    float acc[12][4];
    #pragma unroll
    for (int j = 0; j < 12; j++)
        #pragma unroll
        for (int d = 0; d < 4; d++) acc[j][d] = 0.f;

    // per stage: A 64 rows x 8 chunks (512), B 96 rows x 8 chunks (768)
    #define LOAD_STAGE(s) do {                                                  \
        uint32_t bd_ = sb + ((s) & 1) * BUFSZ;                                  \
        int c0b = (s)*KC16*2;   /* byte offset in a 2048B gmem row */           \
        _Pragma("unroll")                                                       \
        for (int i = 0; i < 4; i++) {                                           \
            int idx = tid + i*128; int row = idx >> 3, q = idx & 7;             \
            cp16(bd_ + row*ROWB + q*16, xg + (size_t)row*CC*2 + c0b + q*16);    \
        }                                                                       \
        _Pragma("unroll")                                                       \
        for (int i = 0; i < 6; i++) {                                           \
            int idx = tid + i*128; int row = idx >> 3, q = idx & 7;             \
            cp16(bd_ + XSZ + row*ROWB + q*16,                                   \
                 wg + (size_t)row*CC*2 + c0b + q*16);                           \
        }                                                                       \
        cp_commit();                                                            \
    } while (0)

    LOAD_STAGE(0);

    const int wr = wid * 16;
    const int tb = t4 * 32;               // byte offset of this thread's window

    for (int s = 0; s < NSTG; s++) {
        cp_wait<0>();
        __syncthreads();
        if (s + 1 < NSTG) LOAD_STAGE(s + 1);

        const char* xs = smemc + (s & 1) * BUFSZ;
        const char* ws = xs + XSZ;

        // A rows g and g+8: 2 LDS.128 each -> 8 half2 regs per row
        uint32_t a0r[8], a1r[8];
        {
            const uint4* p0 = reinterpret_cast<const uint4*>(xs + (wr+g)*ROWB + tb);
            const uint4* p1 = reinterpret_cast<const uint4*>(xs + (wr+g+8)*ROWB + tb);
            uint4 v0 = p0[0], v1 = p0[1];
            a0r[0]=v0.x; a0r[1]=v0.y; a0r[2]=v0.z; a0r[3]=v0.w;
            a0r[4]=v1.x; a0r[5]=v1.y; a0r[6]=v1.z; a0r[7]=v1.w;
            uint4 u0 = p1[0], u1 = p1[1];
            a1r[0]=u0.x; a1r[1]=u0.y; a1r[2]=u0.z; a1r[3]=u0.w;
            a1r[4]=u1.x; a1r[5]=u1.y; a1r[6]=u1.z; a1r[7]=u1.w;
        }

        #pragma unroll
        for (int j = 0; j < 12; j++) {
            const uint4* pb = reinterpret_cast<const uint4*>(
                ws + (8*j+g)*ROWB + tb);
            uint4 w0 = pb[0], w1 = pb[1];
            uint32_t br[8] = { w0.x, w0.y, w0.z, w0.w, w1.x, w1.y, w1.z, w1.w };
            #pragma unroll
            for (int ks = 0; ks < 4; ks++) {
                mma_f16(acc[j],
                        a0r[2*ks], a1r[2*ks], a0r[2*ks+1], a1r[2*ks+1],
                        br[2*ks], br[2*ks+1]);
            }
        }
    }

    float* gr = g_G + ((size_t)b*TT + m0 + (size_t)wid*16)*NCAT;
    #pragma unroll
    for (int j = 0; j < 12; j++) {
        int col = 8*j + 2*t4;
        *reinterpret_cast<float2*>(gr + (size_t)g*NCAT + col) =
            make_float2(acc[j][0], acc[j][1]);
        *reinterpret_cast<float2*>(gr + (size_t)(g+8)*NCAT + col) =
            make_float2(acc[j][2], acc[j][3]);
    }
}

// ---------------- kernel 4: out[t,o] = G[t-1,o] + G[t,32+o] + G[t+1,64+o] -----
__global__ void __launch_bounds__(256) k4_combine(float* __restrict__ out)
{
    const int b = blockIdx.y;
    const int idx = blockIdx.x*256 + threadIdx.x;   // over TT*8
    const int t = idx >> 3, q = idx & 7;
    const float* Gb = g_G + (size_t)b*TT*NCAT;

    float4 acc = make_float4(0.f, 0.f, 0.f, 0.f);
    if (t > 0) {
        float4 v = *reinterpret_cast<const float4*>(Gb + (size_t)(t-1)*NCAT + q*4);
        acc.x += v.x; acc.y += v.y; acc.z += v.z; acc.w += v.w;
    }
    {
        float4 v = *reinterpret_cast<const float4*>(Gb + (size_t)t*NCAT + 32 + q*4);
        acc.x += v.x; acc.y += v.y; acc.z += v.z; acc.w += v.w;
    }
    if (t < TT-1) {
        float4 v = *reinterpret_cast<const float4*>(Gb + (size_t)(t+1)*NCAT + 64 + q*4);
        acc.x += v.x; acc.y += v.y; acc.z += v.z; acc.w += v.w;
    }
    *reinterpret_cast<float4*>(out + ((size_t)b*TT + t)*OO + q*4) = acc;
}

// ---------------- launch ------------------------------------------------------
extern "C" void kernel_launch(void* const* d_in, const int* in_sizes, int n_in,
                              void* d_out, int out_size)
{
    const float* x      = (const float*)d_in[0];
    const float* adj    = (const float*)d_in[1];
    const float* W1     = (const float*)d_in[2];
    const float* W2     = (const float*)d_in[3];
    const float* W3     = (const float*)d_in[4];
    const float* bs     = (const float*)d_in[5];
    const float* Vs     = (const float*)d_in[6];
    const float* conv_w = (const float*)d_in[7];
    float* out = (float*)d_out;

    cudaFuncSetAttribute(k3_mma, cudaFuncAttributeMaxDynamicSharedMemorySize,
                         SMEM_K3);

    k1_reduce<<<dim3(NBLK, BB), 256>>>(x, W1, W2, W3);   // idx 0
    k2a_S<<<BB, 256>>>(bs, Vs);                          // idx 1
    k2b_wt<<<dim3(OO, BB), 256>>>(adj, conv_w);          // idx 2
    k3_mma<<<dim3(TT/MT, BB), 128, SMEM_K3>>>();         // idx 3  <- ncu window
    k4_combine<<<dim3(TT*8/256, BB), 256>>>(out);        // idx 4
}

// round 16
// speedup vs baseline: 1.2773x; 1.0370x over previous
#include <cuda_runtime.h>
#include <cuda_fp16.h>
#include <math.h>
#include <stdint.h>

#define BB 4
#define TT 8192
#define NV 64
#define FF 16
#define CC 1024   // NV*FF
#define OO 32
#define NCAT 96   // 3 taps * 32 outputs
#define NBLK 128  // k1 blocks per batch
#define K1T  64   // t-rows per k1 block

// ---------------- scratch (static device globals; no allocation) -------------
__device__ __align__(16) float  g_pl [BB*NBLK*CC];          // k1 partial lhs
__device__ __align__(16) float  g_pr [BB*NBLK*CC];          // k1 partial r2
__device__ __align__(16) float  g_S  [BB*NV*NV];
__device__ __align__(16) __half g_x16[(size_t)BB*TT*CC];    // fp16 copy of x
__device__ __align__(16) __half g_wt16[BB*NCAT*CC];         // WT[b][oc][c] fp16
__device__ __align__(16) float  g_G  [(size_t)BB*TT*NCAT];  // G[b][t][oc]

// ---------------- helpers -----------------------------------------------------
__device__ __forceinline__ uint32_t smem_u32(const void* p) {
    uint32_t a;
    asm("{ .reg .u64 t; cvta.to.shared.u64 t, %1; cvt.u32.u64 %0, t; }"
        : "=r"(a) : "l"(p));
    return a;
}
__device__ __forceinline__ void cp16(uint32_t dst, const void* src) {
    asm volatile("cp.async.cg.shared.global [%0], [%1], 16;"
                 :: "r"(dst), "l"(src) : "memory");
}
__device__ __forceinline__ void cp_commit() {
    asm volatile("cp.async.commit_group;" ::: "memory");
}
template<int N> __device__ __forceinline__ void cp_wait() {
    asm volatile("cp.async.wait_group %0;" :: "n"(N) : "memory");
}
// fp16 MMA m16n8k16, fp32 accumulate
__device__ __forceinline__ void mma_f16(float* d, uint32_t a0, uint32_t a1,
                                        uint32_t a2, uint32_t a3,
                                        uint32_t b0, uint32_t b1) {
    asm volatile(
        "mma.sync.aligned.m16n8k16.row.col.f32.f16.f16.f32 "
        "{%0,%1,%2,%3}, {%4,%5,%6,%7}, {%8,%9}, {%0,%1,%2,%3};"
        : "+f"(d[0]), "+f"(d[1]), "+f"(d[2]), "+f"(d[3])
        : "r"(a0), "r"(a1), "r"(a2), "r"(a3), "r"(b0), "r"(b1));
}

// ---------------- no-op spacer (shifts ncu capture window onto k1) ------------
__global__ void k_nop() {}

// ---------------- kernel 1: reductions + fp16 transcode -----------------------
__global__ void __launch_bounds__(256) k1_reduce(
    const float* __restrict__ x, const float* __restrict__ W1,
    const float* __restrict__ W2, const float* __restrict__ W3)
{
    const int b  = blockIdx.y;
    const int t0 = blockIdx.x * K1T;
    const int j  = threadIdx.x;
    const int f0 = (j & 3) * 4;

    __shared__ __align__(16) float sW1[K1T];
    __shared__ __align__(16) float sW2T[K1T][20];   // [tt][f], pad 20 (16B-aligned f0)

    if (j < K1T) sW1[j] = W1[t0 + j];
    for (int idx = j; idx < 16*K1T; idx += 256) {
        int f = idx >> 6, tt = idx & (K1T-1);
        sW2T[tt][f] = W2[f*TT + t0 + tt];
    }
    float w3v[4];
    #pragma unroll
    for (int d = 0; d < 4; d++) w3v[d] = W3[f0 + d];
    __syncthreads();

    float lhsacc[4] = {0,0,0,0};
    float r2acc[4]  = {0,0,0,0};
    const float4* xr = reinterpret_cast<const float4*>(
        x + (size_t)b*TT*CC + (size_t)t0*CC) + j;
    __half* x16r = g_x16 + ((size_t)b*TT + t0)*CC + j*4;

    #pragma unroll 8
    for (int tt = 0; tt < K1T; tt++) {
        float4 xv = xr[(size_t)tt*256];
        // fp16 transcode (8B store, 8B-aligned)
        __half2 h0 = __floats2half2_rn(xv.x, xv.y);
        __half2 h1 = __floats2half2_rn(xv.z, xv.w);
        uint2 pk;
        pk.x = *reinterpret_cast<uint32_t*>(&h0);
        pk.y = *reinterpret_cast<uint32_t*>(&h1);
        *reinterpret_cast<uint2*>(x16r + (size_t)tt*CC) = pk;

        float s3 = xv.x*w3v[0] + xv.y*w3v[1] + xv.z*w3v[2] + xv.w*w3v[3];
        s3 += __shfl_xor_sync(0xffffffffu, s3, 1);
        s3 += __shfl_xor_sync(0xffffffffu, s3, 2);
        float w1 = sW1[tt];
        lhsacc[0] += w1*xv.x; lhsacc[1] += w1*xv.y;
        lhsacc[2] += w1*xv.z; lhsacc[3] += w1*xv.w;
        float4 w2v = *reinterpret_cast<const float4*>(&sW2T[tt][f0]);
        r2acc[0] += w2v.x * s3; r2acc[1] += w2v.y * s3;
        r2acc[2] += w2v.z * s3; r2acc[3] += w2v.w * s3;
    }

    size_t base = ((size_t)b*NBLK + blockIdx.x)*CC + j*4;
    *reinterpret_cast<float4*>(g_pl + base) =
        make_float4(lhsacc[0], lhsacc[1], lhsacc[2], lhsacc[3]);
    *reinterpret_cast<float4*>(g_pr + base) =
        make_float4(r2acc[0], r2acc[1], r2acc[2], r2acc[3]);
}

// ---------------- kernel 2a: reduce partials + attention matrix S -------------
__global__ void __launch_bounds__(256) k2a_S(
    const float* __restrict__ bs, const float* __restrict__ Vs)
{
    const int b = blockIdx.x;
    const int tid = threadIdx.x;
    __shared__ __align__(16) float lhs_s[NV*FF];
    __shared__ __align__(16) float R2_s [NV*FF];
    __shared__ __align__(16) float P_s  [NV*NV];
    __shared__ __align__(16) float S0_s [NV*NV];

    {
        const float4* pl = reinterpret_cast<const float4*>(g_pl) + (size_t)b*NBLK*256;
        const float4* pr = reinterpret_cast<const float4*>(g_pr) + (size_t)b*NBLK*256;
        float4 al = make_float4(0,0,0,0), ar = make_float4(0,0,0,0);
        #pragma unroll 8
        for (int blk = 0; blk < NBLK; blk++) {
            float4 v = pl[blk*256 + tid];
            al.x += v.x; al.y += v.y; al.z += v.z; al.w += v.w;
            float4 w = pr[blk*256 + tid];
            ar.x += w.x; ar.y += w.y; ar.z += w.z; ar.w += w.w;
        }
        *reinterpret_cast<float4*>(lhs_s + tid*4) = al;
        *reinterpret_cast<float4*>(R2_s  + tid*4) = ar;
    }
    __syncthreads();

    for (int i = tid; i < NV*NV; i += 256) {
        int m = i >> 6, k = i & 63;
        float acc = 0.f;
        #pragma unroll
        for (int f = 0; f < FF; f++) acc += lhs_s[m*FF+f] * R2_s[k*FF+f];
        acc += bs[i];
        P_s[i] = 1.f / (1.f + expf(-acc));
    }
    __syncthreads();

    for (int i = tid; i < NV*NV; i += 256) {
        int nn = i >> 6, k = i & 63;
        float acc = 0.f;
        #pragma unroll 8
        for (int m = 0; m < NV; m++) acc += Vs[nn*NV+m] * P_s[m*NV+k];
        S0_s[i] = acc;
    }
    __syncthreads();

    if (tid < NV) {
        const int k = tid;
        float mx = -1e30f;
        for (int nn = 0; nn < NV; nn++) mx = fmaxf(mx, S0_s[nn*NV+k]);
        float sum = 0.f;
        for (int nn = 0; nn < NV; nn++) sum += expf(S0_s[nn*NV+k] - mx);
        float inv = 1.f / sum;
        for (int nn = 0; nn < NV; nn++)
            g_S[b*NV*NV + nn*NV + k] = expf(S0_s[nn*NV+k] - mx) * inv;
    }
}

// ---------------- kernel 2b: WT fp16, grid (O, B) -----------------------------
__global__ void __launch_bounds__(256) k2b_wt(
    const float* __restrict__ adj, const float* __restrict__ conv_w)
{
    const int o = blockIdx.x, b = blockIdx.y;
    const int tid = threadIdx.x;
    __shared__ __align__(16) float cws[CC*3];      // conv_w[o][c][tap], 12 KB
    __shared__ __align__(16) float SdT[NV*65];     // [n][m], pad-65

    for (int i = tid; i < CC*3; i += 256)
        cws[i] = conv_w[(size_t)o*CC*3 + i];
    for (int i = tid; i < NV*NV; i += 256) {
        int m = i >> 6, nn = i & 63;
        SdT[nn*65 + m] = g_S[b*NV*NV + i] * adj[nn*NV + nn];
    }
    __syncthreads();

    const int c0 = tid * 4;
    const int m = c0 >> 4, f0 = c0 & 15;
    float acc[3][4];
    #pragma unroll
    for (int t = 0; t < 3; t++)
        #pragma unroll
        for (int j = 0; j < 4; j++) acc[t][j] = 0.f;

    #pragma unroll 4
    for (int n = 0; n < NV; n++) {
        float s = SdT[n*65 + m];
        const float4* cw4 = reinterpret_cast<const float4*>(
            cws + (n*FF + f0)*3);
        float4 w0 = cw4[0], w1 = cw4[1], w2 = cw4[2];
        acc[0][0] += s*w0.x; acc[1][0] += s*w0.y; acc[2][0] += s*w0.z;
        acc[0][1] += s*w0.w; acc[1][1] += s*w1.x; acc[2][1] += s*w1.y;
        acc[0][2] += s*w1.z; acc[1][2] += s*w1.w; acc[2][2] += s*w2.x;
        acc[0][3] += s*w2.y; acc[1][3] += s*w2.z; acc[2][3] += s*w2.w;
    }

    #pragma unroll
    for (int t = 0; t < 3; t++) {
        __half2 h0 = __floats2half2_rn(acc[t][0], acc[t][1]);
        __half2 h1 = __floats2half2_rn(acc[t][2], acc[t][3]);
        uint2 pk;
        pk.x = *reinterpret_cast<uint32_t*>(&h0);
        pk.y = *reinterpret_cast<uint32_t*>(&h1);
        *reinterpret_cast<uint2*>(
            g_wt16 + ((size_t)b*NCAT + t*OO + o)*CC + c0) = pk;
    }
}

// ---------------- kernel 3: G = x16 @ WT16^T, mma.sync fp16 m16n8k16 ----------
#define MT    64
#define KC16  64              // halves per stage
#define NSTG  (CC/KC16)       // 16
#define ROWB  144             // bytes per smem row (9 x 16B chunks)
#define XSZ   (MT*ROWB)       // 9216 B
#define WSZ   (NCAT*ROWB)     // 13824 B
#define BUFSZ (XSZ + WSZ)     // 23040 B
#define SMEM_K3 (2*BUFSZ)     // 46080 B

__global__ void __launch_bounds__(128) k3_mma()
{
    extern __shared__ __align__(16) char smemc[];
    const uint32_t sb = smem_u32(smemc);
    const int tid  = threadIdx.x;
    const int wid  = tid >> 5, lane = tid & 31;
    const int g    = lane >> 2;           // 0..7
    const int t4   = lane & 3;            // 0..3
    const int b    = blockIdx.y;
    const size_t m0 = (size_t)blockIdx.x * MT;

    const char* xg = (const char*)(g_x16 + ((size_t)b*TT + m0)*CC);
    const char* wg = (const char*)(g_wt16 + (size_t)b*NCAT*CC);

    float acc[12][4];
    #pragma unroll
    for (int j = 0; j < 12; j++)
        #pragma unroll
        for (int d = 0; d < 4; d++) acc[j][d] = 0.f;

    #define LOAD_STAGE(s) do {                                                  \
        uint32_t bd_ = sb + ((s) & 1) * BUFSZ;                                  \
        int c0b = (s)*KC16*2;                                                   \
        _Pragma("unroll")                                                       \
        for (int i = 0; i < 4; i++) {                                           \
            int idx = tid + i*128; int row = idx >> 3, q = idx & 7;             \
            cp16(bd_ + row*ROWB + q*16, xg + (size_t)row*CC*2 + c0b + q*16);    \
        }                                                                       \
        _Pragma("unroll")                                                       \
        for (int i = 0; i < 6; i++) {                                           \
            int idx = tid + i*128; int row = idx >> 3, q = idx & 7;             \
            cp16(bd_ + XSZ + row*ROWB + q*16,                                   \
                 wg + (size_t)row*CC*2 + c0b + q*16);                           \
        }                                                                       \
        cp_commit();                                                            \
    } while (0)

    LOAD_STAGE(0);

    const int wr = wid * 16;
    const int tb = t4 * 32;               // byte offset of this thread's window

    for (int s = 0; s < NSTG; s++) {
        cp_wait<0>();
        __syncthreads();
        if (s + 1 < NSTG) LOAD_STAGE(s + 1);

        const char* xs = smemc + (s & 1) * BUFSZ;
        const char* ws = xs + XSZ;

        uint32_t a0r[8], a1r[8];
        {
            const uint4* p0 = reinterpret_cast<const uint4*>(xs + (wr+g)*ROWB + tb);
            const uint4* p1 = reinterpret_cast<const uint4*>(xs + (wr+g+8)*ROWB + tb);
            uint4 v0 = p0[0], v1 = p0[1];
            a0r[0]=v0.x; a0r[1]=v0.y; a0r[2]=v0.z; a0r[3]=v0.w;
            a0r[4]=v1.x; a0r[5]=v1.y; a0r[6]=v1.z; a0r[7]=v1.w;
            uint4 u0 = p1[0], u1 = p1[1];
            a1r[0]=u0.x; a1r[1]=u0.y; a1r[2]=u0.z; a1r[3]=u0.w;
            a1r[4]=u1.x; a1r[5]=u1.y; a1r[6]=u1.z; a1r[7]=u1.w;
        }

        #pragma unroll
        for (int j = 0; j < 12; j++) {
            const uint4* pb = reinterpret_cast<const uint4*>(
                ws + (8*j+g)*ROWB + tb);
            uint4 w0 = pb[0], w1 = pb[1];
            uint32_t br[8] = { w0.x, w0.y, w0.z, w0.w, w1.x, w1.y, w1.z, w1.w };
            #pragma unroll
            for (int ks = 0; ks < 4; ks++) {
                mma_f16(acc[j],
                        a0r[2*ks], a1r[2*ks], a0r[2*ks+1], a1r[2*ks+1],
                        br[2*ks], br[2*ks+1]);
            }
        }
    }

    float* gr = g_G + ((size_t)b*TT + m0 + (size_t)wid*16)*NCAT;
    #pragma unroll
    for (int j = 0; j < 12; j++) {
        int col = 8*j + 2*t4;
        *reinterpret_cast<float2*>(gr + (size_t)g*NCAT + col) =
            make_float2(acc[j][0], acc[j][1]);
        *reinterpret_cast<float2*>(gr + (size_t)(g+8)*NCAT + col) =
            make_float2(acc[j][2], acc[j][3]);
    }
}

// ---------------- kernel 4: out[t,o] = G[t-1,o] + G[t,32+o] + G[t+1,64+o] -----
__global__ void __launch_bounds__(256) k4_combine(float* __restrict__ out)
{
    const int b = blockIdx.y;
    const int idx = blockIdx.x*256 + threadIdx.x;   // over TT*8
    const int t = idx >> 3, q = idx & 7;
    const float* Gb = g_G + (size_t)b*TT*NCAT;

    float4 acc = make_float4(0.f, 0.f, 0.f, 0.f);
    if (t > 0) {
        float4 v = *reinterpret_cast<const float4*>(Gb + (size_t)(t-1)*NCAT + q*4);
        acc.x += v.x; acc.y += v.y; acc.z += v.z; acc.w += v.w;
    }
    {
        float4 v = *reinterpret_cast<const float4*>(Gb + (size_t)t*NCAT + 32 + q*4);
        acc.x += v.x; acc.y += v.y; acc.z += v.z; acc.w += v.w;
    }
    if (t < TT-1) {
        float4 v = *reinterpret_cast<const float4*>(Gb + (size_t)(t+1)*NCAT + 64 + q*4);
        acc.x += v.x; acc.y += v.y; acc.z += v.z; acc.w += v.w;
    }
    *reinterpret_cast<float4*>(out + ((size_t)b*TT + t)*OO + q*4) = acc;
}

// ---------------- launch ------------------------------------------------------
extern "C" void kernel_launch(void* const* d_in, const int* in_sizes, int n_in,
                              void* d_out, int out_size)
{
    const float* x      = (const float*)d_in[0];
    const float* adj    = (const float*)d_in[1];
    const float* W1     = (const float*)d_in[2];
    const float* W2     = (const float*)d_in[3];
    const float* W3     = (const float*)d_in[4];
    const float* W3u    = W3;
    const float* bs     = (const float*)d_in[5];
    const float* Vs     = (const float*)d_in[6];
    const float* conv_w = (const float*)d_in[7];
    float* out = (float*)d_out;
    (void)W3u;

    cudaFuncSetAttribute(k3_mma, cudaFuncAttributeMaxDynamicSharedMemorySize,
                         SMEM_K3);

    k_nop<<<1, 32>>>();                                   // idx 0 (spacer)
    k_nop<<<1, 32>>>();                                   // idx 1 (spacer)
    k_nop<<<1, 32>>>();                                   // idx 2 (spacer)
    k1_reduce<<<dim3(NBLK, BB), 256>>>(x, W1, W2, W3);    // idx 3 <- ncu window
    k2a_S<<<BB, 256>>>(bs, Vs);                           // idx 4
    k2b_wt<<<dim3(OO, BB), 256>>>(adj, conv_w);           // idx 5
    k3_mma<<<dim3(TT/MT, BB), 128, SMEM_K3>>>();          // idx 6
    k4_combine<<<dim3(TT*8/256, BB), 256>>>(out);         // idx 7
}